// round 4
// baseline (speedup 1.0000x reference)
#include <cuda_runtime.h>
#include <cuda_bf16.h>
#include <math.h>

// Problem constants
#define Bb   2
#define Ss   1024
#define Dd   1024
#define Ee   2048
#define Nn   16
#define Rr   64
#define BSr  (Bb * Ss)          // 2048 rows
#define DBCW (Rr + 2 * Nn)      // 96
#define THREED (3 * Dd)         // 3072

// ---------------- scratch (device globals; no allocation in kernel_launch) ----
__device__ float g_sc   [Bb * 2 * Dd];        // silu(c)
__device__ float g_ada  [Bb * THREED];        // shift|scale|gate
__device__ float g_skip [BSr * Dd];
__device__ float g_xn   [BSr * Dd];
__device__ float g_mz   [BSr * Ee];
__device__ float g_mx   [BSr * Ee];
__device__ float g_z1   [BSr * Ee];
__device__ float g_z2   [BSr * Ee];
__device__ float g_dbc1 [BSr * DBCW];
__device__ float g_dbc2 [BSr * DBCW];
__device__ float g_del1 [BSr * Ee];
__device__ float g_del2 [BSr * Ee];
__device__ float g_gg1  [BSr * Ee];
__device__ float g_gg2  [BSr * Ee];
__device__ float g_acmb [BSr * Ee];
__device__ float g_tmp  [BSr * Dd];

// ---------------- helpers -----------------------------------------------------
__device__ __forceinline__ float siluf(float v) {
    return v / (1.0f + expf(-v));
}
__device__ __forceinline__ float softplusf(float v) {
    return (v > 20.0f) ? v : log1pf(expf(v));
}

__device__ __forceinline__ float blockReduceSum(float v, float* sh) {
    int lane = threadIdx.x & 31, wid = threadIdx.x >> 5;
#pragma unroll
    for (int o = 16; o; o >>= 1) v += __shfl_xor_sync(0xffffffffu, v, o);
    __syncthreads();                 // protect sh from prior use
    if (lane == 0) sh[wid] = v;
    __syncthreads();
    if (wid == 0) {
        v = (lane < 8) ? sh[lane] : 0.0f;
#pragma unroll
        for (int o = 4; o; o >>= 1) v += __shfl_xor_sync(0xffffffffu, v, o);
        if (lane == 0) sh[0] = v;
    }
    __syncthreads();
    return sh[0];
}

// ---------------- generic fp32 GEMM: C[M,N] = A[M,K] * B[N,K]^T (+bias) -------
// Tile 128x128x16, 256 threads, 8x8 per thread. epi: 0 = none, 1 = softplus.
__global__ __launch_bounds__(256) void gemm_tn(
    const float* __restrict__ A, int lda,
    const float* __restrict__ Bm, int ldb,
    const float* __restrict__ bias,
    float* __restrict__ C, int ldc,
    int M, int N, int K, int epi)
{
    __shared__ float As[16][128];
    __shared__ float Bs[16][128];

    const int bm = blockIdx.y * 128;
    const int bn = blockIdx.x * 128;
    const int tid = threadIdx.x;
    const int tx = tid & 15;
    const int ty = tid >> 4;

    float acc[8][8];
#pragma unroll
    for (int i = 0; i < 8; i++)
#pragma unroll
        for (int j = 0; j < 8; j++) acc[i][j] = 0.0f;

    const int l0 = tid;
    const int l1 = tid + 256;
    const int ar0 = l0 >> 2, ak0 = (l0 & 3) * 4;
    const int ar1 = l1 >> 2, ak1 = (l1 & 3) * 4;

    for (int k0 = 0; k0 < K; k0 += 16) {
        float4 av0 = make_float4(0, 0, 0, 0), av1 = av0, bv0 = av0, bv1 = av0;
        if (bm + ar0 < M) av0 = *(const float4*)(A + (size_t)(bm + ar0) * lda + k0 + ak0);
        if (bm + ar1 < M) av1 = *(const float4*)(A + (size_t)(bm + ar1) * lda + k0 + ak1);
        if (bn + ar0 < N) bv0 = *(const float4*)(Bm + (size_t)(bn + ar0) * ldb + k0 + ak0);
        if (bn + ar1 < N) bv1 = *(const float4*)(Bm + (size_t)(bn + ar1) * ldb + k0 + ak1);

        __syncthreads();
        As[ak0 + 0][ar0] = av0.x; As[ak0 + 1][ar0] = av0.y;
        As[ak0 + 2][ar0] = av0.z; As[ak0 + 3][ar0] = av0.w;
        As[ak1 + 0][ar1] = av1.x; As[ak1 + 1][ar1] = av1.y;
        As[ak1 + 2][ar1] = av1.z; As[ak1 + 3][ar1] = av1.w;
        Bs[ak0 + 0][ar0] = bv0.x; Bs[ak0 + 1][ar0] = bv0.y;
        Bs[ak0 + 2][ar0] = bv0.z; Bs[ak0 + 3][ar0] = bv0.w;
        Bs[ak1 + 0][ar1] = bv1.x; Bs[ak1 + 1][ar1] = bv1.y;
        Bs[ak1 + 2][ar1] = bv1.z; Bs[ak1 + 3][ar1] = bv1.w;
        __syncthreads();

#pragma unroll
        for (int kk = 0; kk < 16; kk++) {
            float a[8], b[8];
            *(float4*)&a[0] = *(const float4*)&As[kk][ty * 8];
            *(float4*)&a[4] = *(const float4*)&As[kk][ty * 8 + 4];
            *(float4*)&b[0] = *(const float4*)&Bs[kk][tx * 8];
            *(float4*)&b[4] = *(const float4*)&Bs[kk][tx * 8 + 4];
#pragma unroll
            for (int i = 0; i < 8; i++)
#pragma unroll
                for (int j = 0; j < 8; j++) acc[i][j] = fmaf(a[i], b[j], acc[i][j]);
        }
    }

#pragma unroll
    for (int i = 0; i < 8; i++) {
        int row = bm + ty * 8 + i;
        if (row >= M) continue;
#pragma unroll
        for (int j = 0; j < 8; j += 4) {
            int col = bn + tx * 8 + j;
            if (col >= N) continue;   // N is a multiple of 4 in all our calls
            float4 v;
            v.x = acc[i][j + 0] + (bias ? __ldg(bias + col + 0) : 0.0f);
            v.y = acc[i][j + 1] + (bias ? __ldg(bias + col + 1) : 0.0f);
            v.z = acc[i][j + 2] + (bias ? __ldg(bias + col + 2) : 0.0f);
            v.w = acc[i][j + 3] + (bias ? __ldg(bias + col + 3) : 0.0f);
            if (epi == 1) {
                v.x = softplusf(v.x); v.y = softplusf(v.y);
                v.z = softplusf(v.z); v.w = softplusf(v.w);
            }
            *(float4*)(C + (size_t)row * ldc + col) = v;
        }
    }
}

// ---------------- silu(c) ------------------------------------------------------
__global__ void silu_kernel(const float* __restrict__ in, float* __restrict__ out, int n) {
    int i = blockIdx.x * blockDim.x + threadIdx.x;
    if (i < n) out[i] = siluf(in[i]);
}

// ---------------- fused LN1 + modulate(+store skip) + LN2 ----------------------
__global__ __launch_bounds__(256) void ln_mod_kernel(
    const float* __restrict__ x,
    const float* __restrict__ g1, const float* __restrict__ b1,
    const float* __restrict__ g2, const float* __restrict__ b2,
    const float* __restrict__ ada,
    float* __restrict__ skip, float* __restrict__ xn)
{
    __shared__ float sh[8];
    const int row = blockIdx.x;            // 0..2047
    const int b = row >> 10;               // row / S
    const float* xr = x + (size_t)row * Dd;

    float v[4];
#pragma unroll
    for (int j = 0; j < 4; j++) v[j] = xr[threadIdx.x + j * 256];

    float s1 = 0.0f, s2 = 0.0f;
#pragma unroll
    for (int j = 0; j < 4; j++) { s1 += v[j]; s2 += v[j] * v[j]; }
    s1 = blockReduceSum(s1, sh);
    s2 = blockReduceSum(s2, sh);
    float m  = s1 * (1.0f / Dd);
    float rs = rsqrtf(s2 * (1.0f / Dd) - m * m + 1e-5f);

    float t[4];
    s1 = 0.0f; s2 = 0.0f;
#pragma unroll
    for (int j = 0; j < 4; j++) {
        int d = threadIdx.x + j * 256;
        float tt = (v[j] - m) * rs * g1[d] + b1[d];
        tt = tt * (1.0f + ada[b * THREED + Dd + d]) + ada[b * THREED + d];
        t[j] = tt;
        skip[(size_t)row * Dd + d] = tt;
        s1 += tt; s2 += tt * tt;
    }
    s1 = blockReduceSum(s1, sh);
    s2 = blockReduceSum(s2, sh);
    float m2  = s1 * (1.0f / Dd);
    float rs2 = rsqrtf(s2 * (1.0f / Dd) - m2 * m2 + 1e-5f);

#pragma unroll
    for (int j = 0; j < 4; j++) {
        int d = threadIdx.x + j * 256;
        xn[(size_t)row * Dd + d] = (t[j] - m2) * rs2 * g2[d] + b2[d];
    }
}

// ---------------- selective scan -----------------------------------------------
// One half-warp per (b, e): 16 lanes = 16 SSM states. backward=1 scans s
// from S-1 downto 0 (equivalent to flip / scan / flip in the reference).
__global__ __launch_bounds__(256) void scan_kernel(
    const float* __restrict__ delta,   // [B*S, E], softplus already applied
    const float* __restrict__ u,       // [B*S, E]  (z buffer)
    const float* __restrict__ dbc,     // [B*S, 96] (dlt|B|C)
    const float* __restrict__ Alog,    // [E, N]
    const float* __restrict__ Dp,      // [E]
    float* __restrict__ g,             // [B*S, E]
    int backward)
{
    const int w    = (blockIdx.x * blockDim.x + threadIdx.x) >> 5;   // 0..2047
    const int lane = threadIdx.x & 31;
    const int half = lane >> 4;
    const int n    = lane & 15;
    const int f    = w * 2 + half;       // flat (b,e) 0..4095
    const int b    = f >> 11;            // / E
    const int e    = f & (Ee - 1);

    const float A_n  = -__expf(Alog[e * Nn + n]);
    const float Dp_e = Dp[e];
    float h = 0.0f;

    for (int step = 0; step < Ss; step++) {
        const int s = backward ? (Ss - 1 - step) : step;
        const size_t idx = (size_t)b * Ss + s;
        const float dlt = delta[idx * Ee + e];
        const float uu  = u[idx * Ee + e];
        const float Bv  = dbc[idx * DBCW + Rr + n];
        const float Cv  = dbc[idx * DBCW + Rr + Nn + n];

        h = __expf(dlt * A_n) * h + dlt * Bv * uu;
        float y = h * Cv;
        y += __shfl_xor_sync(0xffffffffu, y, 8);
        y += __shfl_xor_sync(0xffffffffu, y, 4);
        y += __shfl_xor_sync(0xffffffffu, y, 2);
        y += __shfl_xor_sync(0xffffffffu, y, 1);
        if (n == 0) g[idx * Ee + e] = y + uu * Dp_e;
    }
}

// ---------------- a = silu(mx) * (g1 + g2) --------------------------------------
__global__ void combine_kernel(const float* __restrict__ mx,
                               const float* __restrict__ gg1,
                               const float* __restrict__ gg2,
                               float* __restrict__ a, int n)
{
    int i = blockIdx.x * blockDim.x + threadIdx.x;
    if (i < n) a[i] = siluf(mx[i]) * (gg1[i] + gg2[i]);
}

// ---------------- out = x + gate * (tmp + skip) ---------------------------------
// (bf was already added as GEMM bias inside tmp)
__global__ void final_kernel(const float* __restrict__ x,
                             const float* __restrict__ ada,
                             const float* __restrict__ tmp,
                             const float* __restrict__ skip,
                             float* __restrict__ out, int n)
{
    int i = blockIdx.x * blockDim.x + threadIdx.x;
    if (i < n) {
        int row = i >> 10;           // / D
        int d   = i & (Dd - 1);
        int b   = row >> 10;         // / S
        float gate = ada[b * THREED + 2 * Dd + d];
        out[i] = x[i] + gate * (tmp[i] + skip[i]);
    }
}

// ---------------- host launcher --------------------------------------------------
extern "C" void kernel_launch(void* const* d_in, const int* in_sizes, int n_in,
                              void* d_out, int out_size)
{
    const float* x     = (const float*)d_in[0];
    const float* c     = (const float*)d_in[1];
    // d_in[2] = w (unused by the reference)
    const float* n1g   = (const float*)d_in[3];
    const float* n1b   = (const float*)d_in[4];
    const float* n2g   = (const float*)d_in[5];
    const float* n2b   = (const float*)d_in[6];
    const float* Wx    = (const float*)d_in[7];
    const float* bx    = (const float*)d_in[8];
    const float* Wz    = (const float*)d_in[9];
    const float* bz    = (const float*)d_in[10];
    const float* Wf    = (const float*)d_in[11];
    const float* bf    = (const float*)d_in[12];
    const float* Wada  = (const float*)d_in[13];
    const float* bada  = (const float*)d_in[14];
    const float* Wc1   = (const float*)d_in[15];
    const float* bc1   = (const float*)d_in[16];
    const float* Wc2   = (const float*)d_in[17];
    const float* bc2   = (const float*)d_in[18];
    const float* Wdbc1 = (const float*)d_in[19];
    const float* Wdt1  = (const float*)d_in[20];
    const float* bdt1  = (const float*)d_in[21];
    const float* Alog1 = (const float*)d_in[22];
    const float* Dp1   = (const float*)d_in[23];
    const float* Wdbc2 = (const float*)d_in[24];
    const float* Wdt2  = (const float*)d_in[25];
    const float* bdt2  = (const float*)d_in[26];
    const float* Alog2 = (const float*)d_in[27];
    const float* Dp2   = (const float*)d_in[28];
    float* out = (float*)d_out;

    float *sc, *ada, *skip, *xn, *mz, *mx, *z1, *z2, *dbc1, *dbc2;
    float *de1, *de2, *gg1, *gg2, *acmb, *tmp;
    cudaGetSymbolAddress((void**)&sc,   g_sc);
    cudaGetSymbolAddress((void**)&ada,  g_ada);
    cudaGetSymbolAddress((void**)&skip, g_skip);
    cudaGetSymbolAddress((void**)&xn,   g_xn);
    cudaGetSymbolAddress((void**)&mz,   g_mz);
    cudaGetSymbolAddress((void**)&mx,   g_mx);
    cudaGetSymbolAddress((void**)&z1,   g_z1);
    cudaGetSymbolAddress((void**)&z2,   g_z2);
    cudaGetSymbolAddress((void**)&dbc1, g_dbc1);
    cudaGetSymbolAddress((void**)&dbc2, g_dbc2);
    cudaGetSymbolAddress((void**)&de1,  g_del1);
    cudaGetSymbolAddress((void**)&de2,  g_del2);
    cudaGetSymbolAddress((void**)&gg1,  g_gg1);
    cudaGetSymbolAddress((void**)&gg2,  g_gg2);
    cudaGetSymbolAddress((void**)&acmb, g_acmb);
    cudaGetSymbolAddress((void**)&tmp,  g_tmp);

    // 1. silu(c)
    silu_kernel<<<(Bb * 2 * Dd + 255) / 256, 256>>>(c, sc, Bb * 2 * Dd);

    // 2. ada = silu(c) @ Wada^T + bada   [2, 3072]
    gemm_tn<<<dim3(THREED / 128, 1), 256>>>(sc, 2 * Dd, Wada, 2 * Dd, bada,
                                            ada, THREED, Bb, THREED, 2 * Dd, 0);

    // 3. LN1 + modulate (-> skip) + LN2 (-> xn)
    ln_mod_kernel<<<BSr, 256>>>(x, n1g, n1b, n2g, n2b, ada, skip, xn);

    // 4/5. mz, mx  [2048, 2048] K=1024
    gemm_tn<<<dim3(Ee / 128, BSr / 128), 256>>>(xn, Dd, Wz, Dd, bz, mz, Ee, BSr, Ee, Dd, 0);
    gemm_tn<<<dim3(Ee / 128, BSr / 128), 256>>>(xn, Dd, Wx, Dd, bx, mx, Ee, BSr, Ee, Dd, 0);

    // 6/7. z1, z2  [2048, 2048] K=2048
    gemm_tn<<<dim3(Ee / 128, BSr / 128), 256>>>(mz, Ee, Wc1, Ee, bc1, z1, Ee, BSr, Ee, Ee, 0);
    gemm_tn<<<dim3(Ee / 128, BSr / 128), 256>>>(mz, Ee, Wc2, Ee, bc2, z2, Ee, BSr, Ee, Ee, 0);

    // 8/9. dbc = z @ Wdbc^T  [2048, 96] K=2048 (no bias)
    gemm_tn<<<dim3(1, BSr / 128), 256>>>(z1, Ee, Wdbc1, Ee, nullptr, dbc1, DBCW, BSr, DBCW, Ee, 0);
    gemm_tn<<<dim3(1, BSr / 128), 256>>>(z2, Ee, Wdbc2, Ee, nullptr, dbc2, DBCW, BSr, DBCW, Ee, 0);

    // 10/11. delta = softplus(dlt @ Wdt^T + bdt)  [2048, 2048] K=64 (A strided in dbc)
    gemm_tn<<<dim3(Ee / 128, BSr / 128), 256>>>(dbc1, DBCW, Wdt1, Rr, bdt1, de1, Ee, BSr, Ee, Rr, 1);
    gemm_tn<<<dim3(Ee / 128, BSr / 128), 256>>>(dbc2, DBCW, Wdt2, Rr, bdt2, de2, Ee, BSr, Ee, Rr, 1);

    // 12/13. selective scans (forward, backward)
    scan_kernel<<<256, 256>>>(de1, z1, dbc1, Alog1, Dp1, gg1, 0);
    scan_kernel<<<256, 256>>>(de2, z2, dbc2, Alog2, Dp2, gg2, 1);

    // 14. acmb = silu(mx) * (gg1 + gg2)
    combine_kernel<<<(BSr * Ee + 255) / 256, 256>>>(mx, gg1, gg2, acmb, BSr * Ee);

    // 15. tmp = acmb @ Wf^T + bf  [2048, 1024] K=2048
    gemm_tn<<<dim3(Dd / 128, BSr / 128), 256>>>(acmb, Ee, Wf, Ee, bf, tmp, Dd, BSr, Dd, Ee, 0);

    // 16. out = x + gate * (tmp + skip)
    final_kernel<<<(BSr * Dd + 255) / 256, 256>>>(x, ada, tmp, skip, out, BSr * Dd);
}

// round 5
// speedup vs baseline: 2.0087x; 2.0087x over previous
#include <cuda_runtime.h>
#include <cuda_bf16.h>
#include <math.h>
#include <stdint.h>

// Problem constants
#define Bb   2
#define Ss   1024
#define Dd   1024
#define Ee   2048
#define Nn   16
#define Rr   64
#define BSr  (Bb * Ss)          // 2048 rows
#define DBCW (Rr + 2 * Nn)      // 96
#define THREED (3 * Dd)         // 3072
#define KSPLIT 8

// ---------------- scratch (device globals; no allocation in kernel_launch) ----
__device__ float g_sc   [Bb * 2 * Dd];
__device__ float g_ada  [Bb * THREED];
__device__ float g_skip [BSr * Dd];
__device__ float g_xn   [BSr * Dd];
__device__ float g_mz   [BSr * Ee];
__device__ float g_mx   [BSr * Ee];
__device__ float g_z1   [BSr * Ee];
__device__ float g_z2   [BSr * Ee];
__device__ float g_dbc1 [BSr * DBCW];
__device__ float g_dbc2 [BSr * DBCW];
__device__ float g_del1 [BSr * Ee];
__device__ float g_del2 [BSr * Ee];
__device__ float g_gg1  [BSr * Ee];
__device__ float g_gg2  [BSr * Ee];
__device__ float g_acmb [BSr * Ee];
__device__ float g_tmp  [BSr * Dd];
__device__ float g_part [KSPLIT * BSr * DBCW];

// ---------------- helpers -----------------------------------------------------
__device__ __forceinline__ float siluf(float v) { return v / (1.0f + expf(-v)); }
__device__ __forceinline__ float softplusf(float v) {
    return (v > 20.0f) ? v : log1pf(expf(v));
}
__device__ __forceinline__ uint32_t f2tf32(float f) {
    uint32_t u;
    asm("cvt.rna.tf32.f32 %0, %1;" : "=r"(u) : "f"(f));
    return u;
}
__device__ __forceinline__ void mma_tf32(float* c, const uint32_t* a, const uint32_t* b) {
    asm volatile(
        "mma.sync.aligned.m16n8k8.row.col.f32.tf32.tf32.f32 "
        "{%0,%1,%2,%3},{%4,%5,%6,%7},{%8,%9},{%0,%1,%2,%3};"
        : "+f"(c[0]), "+f"(c[1]), "+f"(c[2]), "+f"(c[3])
        : "r"(a[0]), "r"(a[1]), "r"(a[2]), "r"(a[3]), "r"(b[0]), "r"(b[1]));
}

__device__ __forceinline__ float blockReduceSum(float v, float* sh) {
    int lane = threadIdx.x & 31, wid = threadIdx.x >> 5;
#pragma unroll
    for (int o = 16; o; o >>= 1) v += __shfl_xor_sync(0xffffffffu, v, o);
    __syncthreads();
    if (lane == 0) sh[wid] = v;
    __syncthreads();
    if (wid == 0) {
        v = (lane < 8) ? sh[lane] : 0.0f;
#pragma unroll
        for (int o = 4; o; o >>= 1) v += __shfl_xor_sync(0xffffffffu, v, o);
        if (lane == 0) sh[0] = v;
    }
    __syncthreads();
    return sh[0];
}

// ---------------- tf32 tensor-core GEMM ----------------------------------------
// C[M,N] = A[M,K] * W[N,K]^T (+bias, +epi). Tile 128x128x32, 256 threads,
// 8 warps (2x4), warp tile 64x32, mma m16n8k8 tf32. Double-buffered SMEM with
// XOR swizzle (conflict-free both on fill and on fragment loads).
// gridDim.z = split-K count; each z writes C + z*partStride (bias applied only
// when gridDim.z == 1). M must be a multiple of 128, N even, K multiple of
// 32*gridDim.z.
__global__ __launch_bounds__(256) void gemm_tf32(
    const float* __restrict__ A, int lda,
    const float* __restrict__ W, int ldb,
    const float* __restrict__ bias,
    float* __restrict__ C, int ldc,
    int M, int N, int K, int epi, int partStride)
{
    extern __shared__ uint32_t smbuf[];
    uint32_t* As = smbuf;           // [2][128*32]
    uint32_t* Bs = smbuf + 8192;    // [2][128*32]

    const int tid  = threadIdx.x;
    const int wid  = tid >> 5, lane = tid & 31;
    const int wm   = wid >> 2, wn = wid & 3;
    const int grp  = lane >> 2, tig = lane & 3;
    const int bm   = blockIdx.y * 128, bn = blockIdx.x * 128;
    const int klen   = K / gridDim.z;
    const int kstart = blockIdx.z * klen;
    const int ntile  = klen >> 5;

    float acc[4][4][4];
#pragma unroll
    for (int i = 0; i < 4; i++)
#pragma unroll
        for (int j = 0; j < 4; j++)
#pragma unroll
            for (int r = 0; r < 4; r++) acc[i][j][r] = 0.0f;

    float4 ra[4], rb[4];

    // ---- load tile 0 into registers, convert, store to smem buf 0 ----
    {
        const int k0 = kstart;
#pragma unroll
        for (int i = 0; i < 4; i++) {
            int f = tid + i * 256;
            int m = f >> 3, kq = (f & 7) * 4;
            ra[i] = *(const float4*)(A + (size_t)(bm + m) * lda + k0 + kq);
            rb[i] = (bn + m < N)
                  ? *(const float4*)(W + (size_t)(bn + m) * ldb + k0 + kq)
                  : make_float4(0.f, 0.f, 0.f, 0.f);
        }
#pragma unroll
        for (int i = 0; i < 4; i++) {
            int f = tid + i * 256;
            int m = f >> 3, kq = (f & 7) * 4;
            int col = kq ^ ((m & 7) << 2);
            uint4 ua = make_uint4(f2tf32(ra[i].x), f2tf32(ra[i].y),
                                  f2tf32(ra[i].z), f2tf32(ra[i].w));
            uint4 ub = make_uint4(f2tf32(rb[i].x), f2tf32(rb[i].y),
                                  f2tf32(rb[i].z), f2tf32(rb[i].w));
            *(uint4*)&As[m * 32 + col] = ua;
            *(uint4*)&Bs[m * 32 + col] = ub;
        }
    }

    const int swz = grp << 2;

    for (int t = 0; t < ntile; t++) {
        const int buf = (t & 1) * 4096;
        __syncthreads();

        if (t + 1 < ntile) {
            const int k0 = kstart + (t + 1) * 32;
#pragma unroll
            for (int i = 0; i < 4; i++) {
                int f = tid + i * 256;
                int m = f >> 3, kq = (f & 7) * 4;
                ra[i] = *(const float4*)(A + (size_t)(bm + m) * lda + k0 + kq);
                rb[i] = (bn + m < N)
                      ? *(const float4*)(W + (size_t)(bn + m) * ldb + k0 + kq)
                      : make_float4(0.f, 0.f, 0.f, 0.f);
            }
        }

#pragma unroll
        for (int ks = 0; ks < 4; ks++) {
            const int kb = ks * 8;
            const int c0 = (kb + tig) ^ swz;
            const int c1 = (kb + tig + 4) ^ swz;
            uint32_t af[4][4], bf[4][2];
#pragma unroll
            for (int mt = 0; mt < 4; mt++) {
                int r0 = (wm * 64 + mt * 16 + grp) * 32;
                af[mt][0] = As[buf + r0 + c0];
                af[mt][1] = As[buf + r0 + 256 + c0];   // +8 rows
                af[mt][2] = As[buf + r0 + c1];
                af[mt][3] = As[buf + r0 + 256 + c1];
            }
#pragma unroll
            for (int nt = 0; nt < 4; nt++) {
                int r0 = (wn * 32 + nt * 8 + grp) * 32;
                bf[nt][0] = Bs[buf + r0 + c0];
                bf[nt][1] = Bs[buf + r0 + c1];
            }
#pragma unroll
            for (int mt = 0; mt < 4; mt++)
#pragma unroll
                for (int nt = 0; nt < 4; nt++)
                    mma_tf32(acc[mt][nt], af[mt], bf[nt]);
        }

        if (t + 1 < ntile) {
            const int obuf = ((t + 1) & 1) * 4096;
#pragma unroll
            for (int i = 0; i < 4; i++) {
                int f = tid + i * 256;
                int m = f >> 3, kq = (f & 7) * 4;
                int col = kq ^ ((m & 7) << 2);
                uint4 ua = make_uint4(f2tf32(ra[i].x), f2tf32(ra[i].y),
                                      f2tf32(ra[i].z), f2tf32(ra[i].w));
                uint4 ub = make_uint4(f2tf32(rb[i].x), f2tf32(rb[i].y),
                                      f2tf32(rb[i].z), f2tf32(rb[i].w));
                *(uint4*)&As[obuf + m * 32 + col] = ua;
                *(uint4*)&Bs[obuf + m * 32 + col] = ub;
            }
        }
    }

    // ---- epilogue ----
    float* Cp = C + (size_t)blockIdx.z * partStride;
    const bool doBias = (bias != nullptr) && (gridDim.z == 1);
#pragma unroll
    for (int mt = 0; mt < 4; mt++) {
#pragma unroll
        for (int nt = 0; nt < 4; nt++) {
            int row = bm + wm * 64 + mt * 16 + grp;
            int col = bn + wn * 32 + nt * 8 + tig * 2;
            if (col >= N) continue;
            float b0 = doBias ? __ldg(bias + col) : 0.0f;
            float b1 = doBias ? __ldg(bias + col + 1) : 0.0f;
            float v0 = acc[mt][nt][0] + b0, v1 = acc[mt][nt][1] + b1;
            float v2 = acc[mt][nt][2] + b0, v3 = acc[mt][nt][3] + b1;
            if (epi == 1) {
                v0 = softplusf(v0); v1 = softplusf(v1);
                v2 = softplusf(v2); v3 = softplusf(v3);
            }
            float2 lo = make_float2(v0, v1), hi = make_float2(v2, v3);
            *(float2*)&Cp[(size_t)row * ldc + col] = lo;
            *(float2*)&Cp[(size_t)(row + 8) * ldc + col] = hi;
        }
    }
}

// ---------------- split-K reduction ---------------------------------------------
__global__ void reduce_splitk(const float* __restrict__ part,
                              float* __restrict__ out, int n)
{
    int i = blockIdx.x * blockDim.x + threadIdx.x;
    if (i < n) {
        float s = 0.0f;
#pragma unroll
        for (int z = 0; z < KSPLIT; z++) s += part[(size_t)z * n + i];
        out[i] = s;
    }
}

// ---------------- small fp32 GEMM for ada (M=2) ---------------------------------
__global__ __launch_bounds__(256) void gemm_tn(
    const float* __restrict__ A, int lda,
    const float* __restrict__ Bm, int ldb,
    const float* __restrict__ bias,
    float* __restrict__ C, int ldc,
    int M, int N, int K)
{
    __shared__ float As[16][128];
    __shared__ float Bs[16][128];
    const int bm = blockIdx.y * 128;
    const int bn = blockIdx.x * 128;
    const int tid = threadIdx.x;
    const int tx = tid & 15;
    const int ty = tid >> 4;

    float acc[8][8];
#pragma unroll
    for (int i = 0; i < 8; i++)
#pragma unroll
        for (int j = 0; j < 8; j++) acc[i][j] = 0.0f;

    const int ar0 = tid >> 2, ak0 = (tid & 3) * 4;
    const int l1 = tid + 256;
    const int ar1 = l1 >> 2, ak1 = (l1 & 3) * 4;

    for (int k0 = 0; k0 < K; k0 += 16) {
        float4 av0 = make_float4(0, 0, 0, 0), av1 = av0, bv0 = av0, bv1 = av0;
        if (bm + ar0 < M) av0 = *(const float4*)(A + (size_t)(bm + ar0) * lda + k0 + ak0);
        if (bm + ar1 < M) av1 = *(const float4*)(A + (size_t)(bm + ar1) * lda + k0 + ak1);
        if (bn + ar0 < N) bv0 = *(const float4*)(Bm + (size_t)(bn + ar0) * ldb + k0 + ak0);
        if (bn + ar1 < N) bv1 = *(const float4*)(Bm + (size_t)(bn + ar1) * ldb + k0 + ak1);
        __syncthreads();
        As[ak0 + 0][ar0] = av0.x; As[ak0 + 1][ar0] = av0.y;
        As[ak0 + 2][ar0] = av0.z; As[ak0 + 3][ar0] = av0.w;
        As[ak1 + 0][ar1] = av1.x; As[ak1 + 1][ar1] = av1.y;
        As[ak1 + 2][ar1] = av1.z; As[ak1 + 3][ar1] = av1.w;
        Bs[ak0 + 0][ar0] = bv0.x; Bs[ak0 + 1][ar0] = bv0.y;
        Bs[ak0 + 2][ar0] = bv0.z; Bs[ak0 + 3][ar0] = bv0.w;
        Bs[ak1 + 0][ar1] = bv1.x; Bs[ak1 + 1][ar1] = bv1.y;
        Bs[ak1 + 2][ar1] = bv1.z; Bs[ak1 + 3][ar1] = bv1.w;
        __syncthreads();
#pragma unroll
        for (int kk = 0; kk < 16; kk++) {
            float a[8], b[8];
            *(float4*)&a[0] = *(const float4*)&As[kk][ty * 8];
            *(float4*)&a[4] = *(const float4*)&As[kk][ty * 8 + 4];
            *(float4*)&b[0] = *(const float4*)&Bs[kk][tx * 8];
            *(float4*)&b[4] = *(const float4*)&Bs[kk][tx * 8 + 4];
#pragma unroll
            for (int i = 0; i < 8; i++)
#pragma unroll
                for (int j = 0; j < 8; j++) acc[i][j] = fmaf(a[i], b[j], acc[i][j]);
        }
    }
#pragma unroll
    for (int i = 0; i < 8; i++) {
        int row = bm + ty * 8 + i;
        if (row >= M) continue;
#pragma unroll
        for (int j = 0; j < 8; j += 4) {
            int col = bn + tx * 8 + j;
            if (col >= N) continue;
            float4 v;
            v.x = acc[i][j + 0] + (bias ? __ldg(bias + col + 0) : 0.0f);
            v.y = acc[i][j + 1] + (bias ? __ldg(bias + col + 1) : 0.0f);
            v.z = acc[i][j + 2] + (bias ? __ldg(bias + col + 2) : 0.0f);
            v.w = acc[i][j + 3] + (bias ? __ldg(bias + col + 3) : 0.0f);
            *(float4*)(C + (size_t)row * ldc + col) = v;
        }
    }
}

// ---------------- silu(c) ------------------------------------------------------
__global__ void silu_kernel(const float* __restrict__ in, float* __restrict__ out, int n) {
    int i = blockIdx.x * blockDim.x + threadIdx.x;
    if (i < n) out[i] = siluf(in[i]);
}

// ---------------- fused LN1 + modulate(+store skip) + LN2 ----------------------
__global__ __launch_bounds__(256) void ln_mod_kernel(
    const float* __restrict__ x,
    const float* __restrict__ g1, const float* __restrict__ b1,
    const float* __restrict__ g2, const float* __restrict__ b2,
    const float* __restrict__ ada,
    float* __restrict__ skip, float* __restrict__ xn)
{
    __shared__ float sh[8];
    const int row = blockIdx.x;
    const int b = row >> 10;
    const float* xr = x + (size_t)row * Dd;

    float v[4];
#pragma unroll
    for (int j = 0; j < 4; j++) v[j] = xr[threadIdx.x + j * 256];

    float s1 = 0.0f, s2 = 0.0f;
#pragma unroll
    for (int j = 0; j < 4; j++) { s1 += v[j]; s2 += v[j] * v[j]; }
    s1 = blockReduceSum(s1, sh);
    s2 = blockReduceSum(s2, sh);
    float m  = s1 * (1.0f / Dd);
    float rs = rsqrtf(s2 * (1.0f / Dd) - m * m + 1e-5f);

    float t[4];
    s1 = 0.0f; s2 = 0.0f;
#pragma unroll
    for (int j = 0; j < 4; j++) {
        int d = threadIdx.x + j * 256;
        float tt = (v[j] - m) * rs * g1[d] + b1[d];
        tt = tt * (1.0f + ada[b * THREED + Dd + d]) + ada[b * THREED + d];
        t[j] = tt;
        skip[(size_t)row * Dd + d] = tt;
        s1 += tt; s2 += tt * tt;
    }
    s1 = blockReduceSum(s1, sh);
    s2 = blockReduceSum(s2, sh);
    float m2  = s1 * (1.0f / Dd);
    float rs2 = rsqrtf(s2 * (1.0f / Dd) - m2 * m2 + 1e-5f);

#pragma unroll
    for (int j = 0; j < 4; j++) {
        int d = threadIdx.x + j * 256;
        xn[(size_t)row * Dd + d] = (t[j] - m2) * rs2 * g2[d] + b2[d];
    }
}

// ---------------- merged selective scans (both branches in one launch) ----------
// One half-warp per (branch, b, e): 16 lanes = 16 SSM states. Branch 1 scans
// s in reverse (flip/scan/flip == reverse scan).
__global__ __launch_bounds__(256) void scan2_kernel(
    const float* __restrict__ de1, const float* __restrict__ z1,
    const float* __restrict__ dbc1, const float* __restrict__ Alog1,
    const float* __restrict__ Dp1, float* __restrict__ gg1,
    const float* __restrict__ de2, const float* __restrict__ z2,
    const float* __restrict__ dbc2, const float* __restrict__ Alog2,
    const float* __restrict__ Dp2, float* __restrict__ gg2)
{
    const int w    = (blockIdx.x * blockDim.x + threadIdx.x) >> 5;   // 0..4095
    const int lane = threadIdx.x & 31;
    const int half = lane >> 4;
    const int n    = lane & 15;
    const int f    = w * 2 + half;          // 0..8191
    const int br   = f >> 12;               // branch
    const int b    = (f >> 11) & 1;
    const int e    = f & (Ee - 1);

    const float* delta = br ? de2  : de1;
    const float* u     = br ? z2   : z1;
    const float* dbc   = br ? dbc2 : dbc1;
    const float* Alog  = br ? Alog2 : Alog1;
    const float* Dp    = br ? Dp2  : Dp1;
    float*       g     = br ? gg2  : gg1;

    const float A_n  = -__expf(Alog[e * Nn + n]);
    const float Dp_e = Dp[e];
    float h = 0.0f;

    for (int step = 0; step < Ss; step++) {
        const int s = br ? (Ss - 1 - step) : step;
        const size_t idx = (size_t)b * Ss + s;
        const float dlt = delta[idx * Ee + e];
        const float uu  = u[idx * Ee + e];
        const float Bv  = dbc[idx * DBCW + Rr + n];
        const float Cv  = dbc[idx * DBCW + Rr + Nn + n];

        h = __expf(dlt * A_n) * h + dlt * Bv * uu;
        float y = h * Cv;
        y += __shfl_xor_sync(0xffffffffu, y, 8);
        y += __shfl_xor_sync(0xffffffffu, y, 4);
        y += __shfl_xor_sync(0xffffffffu, y, 2);
        y += __shfl_xor_sync(0xffffffffu, y, 1);
        if (n == 0) g[idx * Ee + e] = y + uu * Dp_e;
    }
}

// ---------------- a = silu(mx) * (g1 + g2) --------------------------------------
__global__ void combine_kernel(const float* __restrict__ mx,
                               const float* __restrict__ gg1,
                               const float* __restrict__ gg2,
                               float* __restrict__ a, int n)
{
    int i = blockIdx.x * blockDim.x + threadIdx.x;
    if (i < n) a[i] = siluf(mx[i]) * (gg1[i] + gg2[i]);
}

// ---------------- out = x + gate * (tmp + skip) ---------------------------------
__global__ void final_kernel(const float* __restrict__ x,
                             const float* __restrict__ ada,
                             const float* __restrict__ tmp,
                             const float* __restrict__ skip,
                             float* __restrict__ out, int n)
{
    int i = blockIdx.x * blockDim.x + threadIdx.x;
    if (i < n) {
        int row = i >> 10;
        int d   = i & (Dd - 1);
        int b   = row >> 10;
        float gate = ada[b * THREED + 2 * Dd + d];
        out[i] = x[i] + gate * (tmp[i] + skip[i]);
    }
}

// ---------------- host launcher --------------------------------------------------
extern "C" void kernel_launch(void* const* d_in, const int* in_sizes, int n_in,
                              void* d_out, int out_size)
{
    const float* x     = (const float*)d_in[0];
    const float* c     = (const float*)d_in[1];
    const float* n1g   = (const float*)d_in[3];
    const float* n1b   = (const float*)d_in[4];
    const float* n2g   = (const float*)d_in[5];
    const float* n2b   = (const float*)d_in[6];
    const float* Wx    = (const float*)d_in[7];
    const float* bx    = (const float*)d_in[8];
    const float* Wz    = (const float*)d_in[9];
    const float* bz    = (const float*)d_in[10];
    const float* Wf    = (const float*)d_in[11];
    const float* bf    = (const float*)d_in[12];
    const float* Wada  = (const float*)d_in[13];
    const float* bada  = (const float*)d_in[14];
    const float* Wc1   = (const float*)d_in[15];
    const float* bc1   = (const float*)d_in[16];
    const float* Wc2   = (const float*)d_in[17];
    const float* bc2   = (const float*)d_in[18];
    const float* Wdbc1 = (const float*)d_in[19];
    const float* Wdt1  = (const float*)d_in[20];
    const float* bdt1  = (const float*)d_in[21];
    const float* Alog1 = (const float*)d_in[22];
    const float* Dp1   = (const float*)d_in[23];
    const float* Wdbc2 = (const float*)d_in[24];
    const float* Wdt2  = (const float*)d_in[25];
    const float* bdt2  = (const float*)d_in[26];
    const float* Alog2 = (const float*)d_in[27];
    const float* Dp2   = (const float*)d_in[28];
    float* out = (float*)d_out;

    float *sc, *ada, *skip, *xn, *mz, *mx, *z1, *z2, *dbc1, *dbc2;
    float *de1, *de2, *gg1, *gg2, *acmb, *tmp, *part;
    cudaGetSymbolAddress((void**)&sc,   g_sc);
    cudaGetSymbolAddress((void**)&ada,  g_ada);
    cudaGetSymbolAddress((void**)&skip, g_skip);
    cudaGetSymbolAddress((void**)&xn,   g_xn);
    cudaGetSymbolAddress((void**)&mz,   g_mz);
    cudaGetSymbolAddress((void**)&mx,   g_mx);
    cudaGetSymbolAddress((void**)&z1,   g_z1);
    cudaGetSymbolAddress((void**)&z2,   g_z2);
    cudaGetSymbolAddress((void**)&dbc1, g_dbc1);
    cudaGetSymbolAddress((void**)&dbc2, g_dbc2);
    cudaGetSymbolAddress((void**)&de1,  g_del1);
    cudaGetSymbolAddress((void**)&de2,  g_del2);
    cudaGetSymbolAddress((void**)&gg1,  g_gg1);
    cudaGetSymbolAddress((void**)&gg2,  g_gg2);
    cudaGetSymbolAddress((void**)&acmb, g_acmb);
    cudaGetSymbolAddress((void**)&tmp,  g_tmp);
    cudaGetSymbolAddress((void**)&part, g_part);

    const int SMEM = 65536;
    cudaFuncSetAttribute(gemm_tf32, cudaFuncAttributeMaxDynamicSharedMemorySize, SMEM);

    // 1. silu(c)
    silu_kernel<<<(Bb * 2 * Dd + 255) / 256, 256>>>(c, sc, Bb * 2 * Dd);

    // 2. ada = silu(c) @ Wada^T + bada   [2, 3072]  (tiny M -> fp32 SIMT)
    gemm_tn<<<dim3(THREED / 128, 1), 256>>>(sc, 2 * Dd, Wada, 2 * Dd, bada,
                                            ada, THREED, Bb, THREED, 2 * Dd);

    // 3. LN1 + modulate (-> skip) + LN2 (-> xn)
    ln_mod_kernel<<<BSr, 256>>>(x, n1g, n1b, n2g, n2b, ada, skip, xn);

    // 4/5. mz, mx  [2048, 2048] K=1024  (tf32 TC)
    gemm_tf32<<<dim3(Ee / 128, BSr / 128, 1), 256, SMEM>>>(
        xn, Dd, Wz, Dd, bz, mz, Ee, BSr, Ee, Dd, 0, 0);
    gemm_tf32<<<dim3(Ee / 128, BSr / 128, 1), 256, SMEM>>>(
        xn, Dd, Wx, Dd, bx, mx, Ee, BSr, Ee, Dd, 0, 0);

    // 6/7. z1, z2  [2048, 2048] K=2048  (tf32 TC)
    gemm_tf32<<<dim3(Ee / 128, BSr / 128, 1), 256, SMEM>>>(
        mz, Ee, Wc1, Ee, bc1, z1, Ee, BSr, Ee, Ee, 0, 0);
    gemm_tf32<<<dim3(Ee / 128, BSr / 128, 1), 256, SMEM>>>(
        mz, Ee, Wc2, Ee, bc2, z2, Ee, BSr, Ee, Ee, 0, 0);

    // 8/9. dbc = z @ Wdbc^T  [2048, 96] K=2048  (tf32 TC, split-K=8, no bias)
    gemm_tf32<<<dim3(1, BSr / 128, KSPLIT), 256, SMEM>>>(
        z1, Ee, Wdbc1, Ee, nullptr, part, DBCW, BSr, DBCW, Ee, 0, BSr * DBCW);
    reduce_splitk<<<(BSr * DBCW + 255) / 256, 256>>>(part, dbc1, BSr * DBCW);
    gemm_tf32<<<dim3(1, BSr / 128, KSPLIT), 256, SMEM>>>(
        z2, Ee, Wdbc2, Ee, nullptr, part, DBCW, BSr, DBCW, Ee, 0, BSr * DBCW);
    reduce_splitk<<<(BSr * DBCW + 255) / 256, 256>>>(part, dbc2, BSr * DBCW);

    // 10/11. delta = softplus(dlt @ Wdt^T + bdt)  [2048, 2048] K=64 (tf32 TC)
    gemm_tf32<<<dim3(Ee / 128, BSr / 128, 1), 256, SMEM>>>(
        dbc1, DBCW, Wdt1, Rr, bdt1, de1, Ee, BSr, Ee, Rr, 1, 0);
    gemm_tf32<<<dim3(Ee / 128, BSr / 128, 1), 256, SMEM>>>(
        dbc2, DBCW, Wdt2, Rr, bdt2, de2, Ee, BSr, Ee, Rr, 1, 0);

    // 12. both selective scans in one launch (fwd branch 0, bwd branch 1)
    scan2_kernel<<<512, 256>>>(de1, z1, dbc1, Alog1, Dp1, gg1,
                               de2, z2, dbc2, Alog2, Dp2, gg2);

    // 13. acmb = silu(mx) * (gg1 + gg2)
    combine_kernel<<<(BSr * Ee + 255) / 256, 256>>>(mx, gg1, gg2, acmb, BSr * Ee);

    // 14. tmp = acmb @ Wf^T + bf  [2048, 1024] K=2048 (tf32 TC)
    gemm_tf32<<<dim3(Dd / 128, BSr / 128, 1), 256, SMEM>>>(
        acmb, Ee, Wf, Ee, bf, tmp, Dd, BSr, Dd, Ee, 0, 0);

    // 15. out = x + gate * (tmp + skip)
    final_kernel<<<(BSr * Dd + 255) / 256, 256>>>(x, ada, tmp, skip, out, BSr * Dd);
}

// round 6
// speedup vs baseline: 2.1112x; 1.0511x over previous
#include <cuda_runtime.h>
#include <cuda_bf16.h>
#include <math.h>
#include <stdint.h>

// Problem constants
#define Bb   2
#define Ss   1024
#define Dd   1024
#define Ee   2048
#define Nn   16
#define Rr   64
#define BSr  (Bb * Ss)          // 2048 rows
#define DBCW (Rr + 2 * Nn)      // 96
#define THREED (3 * Dd)         // 3072
#define KSPLIT 8

// ---------------- scratch (device globals; no allocation in kernel_launch) ----
__device__ float g_ada  [Bb * THREED];
__device__ float g_skip [BSr * Dd];
__device__ float g_xn   [BSr * Dd];
__device__ float g_mz   [BSr * Ee];
__device__ float g_mx   [BSr * Ee];
__device__ float g_z1   [BSr * Ee];
__device__ float g_z2   [BSr * Ee];
__device__ float g_dbc1 [BSr * DBCW];
__device__ float g_dbc2 [BSr * DBCW];
__device__ float g_del1 [BSr * Ee];
__device__ float g_del2 [BSr * Ee];
__device__ float g_gg1  [BSr * Ee];
__device__ float g_gg2  [BSr * Ee];
__device__ float g_acmb [BSr * Ee];
__device__ float g_tmp  [BSr * Dd];
__device__ float g_part [KSPLIT * BSr * DBCW];
// pre-rounded (tf32) weights
__device__ float g_wz   [Ee * Dd];
__device__ float g_wx   [Ee * Dd];
__device__ float g_wc1  [Ee * Ee];
__device__ float g_wc2  [Ee * Ee];
__device__ float g_wdbc1[DBCW * Ee];
__device__ float g_wdbc2[DBCW * Ee];
__device__ float g_wdt1 [Ee * Rr];
__device__ float g_wdt2 [Ee * Rr];
__device__ float g_wf   [Dd * Ee];

// ---------------- helpers -----------------------------------------------------
__device__ __forceinline__ float siluf(float v) { return v / (1.0f + __expf(-v)); }
__device__ __forceinline__ float softplusf(float v) {
    return (v > 20.0f) ? v : log1pf(__expf(v));
}
__device__ __forceinline__ uint32_t f2tf32(float f) {
    uint32_t u;
    asm("cvt.rna.tf32.f32 %0, %1;" : "=r"(u) : "f"(f));
    return u;
}
__device__ __forceinline__ float roundtf(float f) {
    return __uint_as_float(f2tf32(f));
}
__device__ __forceinline__ void mma_tf32(float* c, const uint32_t* a, const uint32_t* b) {
    asm volatile(
        "mma.sync.aligned.m16n8k8.row.col.f32.tf32.tf32.f32 "
        "{%0,%1,%2,%3},{%4,%5,%6,%7},{%8,%9},{%0,%1,%2,%3};"
        : "+f"(c[0]), "+f"(c[1]), "+f"(c[2]), "+f"(c[3])
        : "r"(a[0]), "r"(a[1]), "r"(a[2]), "r"(a[3]), "r"(b[0]), "r"(b[1]));
}
#define CP16(dst, src, sz) \
    asm volatile("cp.async.cg.shared.global [%0], [%1], 16, %2;" \
                 :: "r"(dst), "l"(src), "r"(sz))

__device__ __forceinline__ float blockReduceSum(float v, float* sh) {
    int lane = threadIdx.x & 31, wid = threadIdx.x >> 5;
#pragma unroll
    for (int o = 16; o; o >>= 1) v += __shfl_xor_sync(0xffffffffu, v, o);
    __syncthreads();
    if (lane == 0) sh[wid] = v;
    __syncthreads();
    if (wid == 0) {
        v = (lane < 8) ? sh[lane] : 0.0f;
#pragma unroll
        for (int o = 4; o; o >>= 1) v += __shfl_xor_sync(0xffffffffu, v, o);
        if (lane == 0) sh[0] = v;
    }
    __syncthreads();
    return sh[0];
}

// ---------------- weight pre-round to tf32 --------------------------------------
__global__ void round_tf32_kernel(const float4* __restrict__ in,
                                  float4* __restrict__ out, int n4)
{
    int i = blockIdx.x * blockDim.x + threadIdx.x;
    if (i < n4) {
        float4 v = in[i];
        v.x = roundtf(v.x); v.y = roundtf(v.y);
        v.z = roundtf(v.z); v.w = roundtf(v.w);
        out[i] = v;
    }
}

// ---------------- tf32 tensor-core GEMM (cp.async, pre-rounded inputs) ----------
// C[M,N] = A[M,K] * W[N,K]^T (+bias, +epi). Tile 128x128x32, 256 threads,
// 8 warps (2x4), warp tile 64x32, mma m16n8k8 tf32. 2-stage cp.async pipeline,
// XOR-swizzled SMEM. A and W must already be tf32-rounded (low 13 bits zero).
// epi: 0 none, 1 softplus, 2 round-to-tf32 on store.
// gridDim.z = split-K; each z writes C + z*partStride (bias only if gridDim.z==1).
__global__ __launch_bounds__(256, 2) void gemm_tf32(
    const float* __restrict__ A, int lda,
    const float* __restrict__ W, int ldb,
    const float* __restrict__ bias,
    float* __restrict__ C, int ldc,
    int M, int N, int K, int epi, int partStride)
{
    extern __shared__ float smf[];
    float* As = smf;            // [2][128*32]
    float* Bs = smf + 8192;     // [2][128*32]

    const int tid  = threadIdx.x;
    const int wid  = tid >> 5, lane = tid & 31;
    const int wm   = wid >> 2, wn = wid & 3;
    const int grp  = lane >> 2, tig = lane & 3;
    const int bm   = blockIdx.y * 128, bn = blockIdx.x * 128;
    const int klen   = K / gridDim.z;
    const int kstart = blockIdx.z * klen;
    const int ntile  = klen >> 5;

    float acc[4][4][4];
#pragma unroll
    for (int i = 0; i < 4; i++)
#pragma unroll
        for (int j = 0; j < 4; j++)
#pragma unroll
            for (int r = 0; r < 4; r++) acc[i][j][r] = 0.0f;

    // per-thread cp.async source/dest setup
    uint32_t aSm[4], bSm[4], bSz[4];
    const float* aP[4];
    const float* bP[4];
    const uint32_t sA = (uint32_t)__cvta_generic_to_shared(As);
    const uint32_t sB = (uint32_t)__cvta_generic_to_shared(Bs);
#pragma unroll
    for (int i = 0; i < 4; i++) {
        int f = tid + i * 256;
        int m = f >> 3, kq = (f & 7) * 4;
        int col = kq ^ ((m & 7) << 2);
        aSm[i] = sA + (uint32_t)(m * 32 + col) * 4u;
        bSm[i] = sB + (uint32_t)(m * 32 + col) * 4u;
        aP[i]  = A + (size_t)(bm + m) * lda + kstart + kq;
        int brow = bn + m;
        bSz[i] = (brow < N) ? 16u : 0u;
        if (brow >= N) brow = N - 1;            // keep address in-bounds
        bP[i]  = W + (size_t)brow * ldb + kstart + kq;
    }

    // prologue: stage 0
#pragma unroll
    for (int i = 0; i < 4; i++) {
        CP16(aSm[i], aP[i], 16u);
        CP16(bSm[i], bP[i], bSz[i]);
        aP[i] += 32; bP[i] += 32;
    }
    asm volatile("cp.async.commit_group;");

    const int swz = grp << 2;

    for (int t = 0; t < ntile; t++) {
        if (t + 1 < ntile) {
            const uint32_t so = (uint32_t)(((t + 1) & 1) * 16384);
#pragma unroll
            for (int i = 0; i < 4; i++) {
                CP16(aSm[i] + so, aP[i], 16u);
                CP16(bSm[i] + so, bP[i], bSz[i]);
                aP[i] += 32; bP[i] += 32;
            }
            asm volatile("cp.async.commit_group;");
            asm volatile("cp.async.wait_group 1;");
        } else {
            asm volatile("cp.async.wait_group 0;");
        }
        __syncthreads();

        const int buf = (t & 1) * 4096;
#pragma unroll
        for (int ks = 0; ks < 4; ks++) {
            const int kb = ks * 8;
            const int c0 = (kb + tig) ^ swz;
            const int c1 = (kb + tig + 4) ^ swz;
            uint32_t af[4][4], bf[4][2];
#pragma unroll
            for (int mt = 0; mt < 4; mt++) {
                int r0 = (wm * 64 + mt * 16 + grp) * 32;
                af[mt][0] = __float_as_uint(As[buf + r0 + c0]);
                af[mt][1] = __float_as_uint(As[buf + r0 + 256 + c0]);
                af[mt][2] = __float_as_uint(As[buf + r0 + c1]);
                af[mt][3] = __float_as_uint(As[buf + r0 + 256 + c1]);
            }
#pragma unroll
            for (int nt = 0; nt < 4; nt++) {
                int r0 = (wn * 32 + nt * 8 + grp) * 32;
                bf[nt][0] = __float_as_uint(Bs[buf + r0 + c0]);
                bf[nt][1] = __float_as_uint(Bs[buf + r0 + c1]);
            }
#pragma unroll
            for (int mt = 0; mt < 4; mt++)
#pragma unroll
                for (int nt = 0; nt < 4; nt++)
                    mma_tf32(acc[mt][nt], af[mt], bf[nt]);
        }
        __syncthreads();
    }

    // ---- epilogue ----
    float* Cp = C + (size_t)blockIdx.z * partStride;
    const bool doBias = (bias != nullptr) && (gridDim.z == 1);
#pragma unroll
    for (int mt = 0; mt < 4; mt++) {
#pragma unroll
        for (int nt = 0; nt < 4; nt++) {
            int row = bm + wm * 64 + mt * 16 + grp;
            int col = bn + wn * 32 + nt * 8 + tig * 2;
            if (col >= N) continue;
            float b0 = doBias ? __ldg(bias + col) : 0.0f;
            float b1 = doBias ? __ldg(bias + col + 1) : 0.0f;
            float v0 = acc[mt][nt][0] + b0, v1 = acc[mt][nt][1] + b1;
            float v2 = acc[mt][nt][2] + b0, v3 = acc[mt][nt][3] + b1;
            if (epi == 1) {
                v0 = softplusf(v0); v1 = softplusf(v1);
                v2 = softplusf(v2); v3 = softplusf(v3);
            } else if (epi == 2) {
                v0 = roundtf(v0); v1 = roundtf(v1);
                v2 = roundtf(v2); v3 = roundtf(v3);
            }
            float2 lo = make_float2(v0, v1), hi = make_float2(v2, v3);
            *(float2*)&Cp[(size_t)row * ldc + col] = lo;
            *(float2*)&Cp[(size_t)(row + 8) * ldc + col] = hi;
        }
    }
}

// ---------------- split-K reduction (rounds output to tf32) ---------------------
__global__ void reduce_splitk(const float* __restrict__ part,
                              float* __restrict__ out, int n)
{
    int i = blockIdx.x * blockDim.x + threadIdx.x;
    if (i < n) {
        float s = 0.0f;
#pragma unroll
        for (int z = 0; z < KSPLIT; z++) s += part[(size_t)z * n + i];
        out[i] = roundtf(s);
    }
}

// ---------------- small fp32 GEMM for ada (M=2), optional silu on A -------------
__global__ __launch_bounds__(256) void gemm_tn(
    const float* __restrict__ A, int lda,
    const float* __restrict__ Bm, int ldb,
    const float* __restrict__ bias,
    float* __restrict__ C, int ldc,
    int M, int N, int K, int siluA)
{
    __shared__ float As[16][128];
    __shared__ float Bs[16][128];
    const int bm = blockIdx.y * 128;
    const int bn = blockIdx.x * 128;
    const int tid = threadIdx.x;
    const int tx = tid & 15;
    const int ty = tid >> 4;

    float acc[8][8];
#pragma unroll
    for (int i = 0; i < 8; i++)
#pragma unroll
        for (int j = 0; j < 8; j++) acc[i][j] = 0.0f;

    const int ar0 = tid >> 2, ak0 = (tid & 3) * 4;
    const int l1 = tid + 256;
    const int ar1 = l1 >> 2, ak1 = (l1 & 3) * 4;

    for (int k0 = 0; k0 < K; k0 += 16) {
        float4 av0 = make_float4(0, 0, 0, 0), av1 = av0, bv0 = av0, bv1 = av0;
        if (bm + ar0 < M) av0 = *(const float4*)(A + (size_t)(bm + ar0) * lda + k0 + ak0);
        if (bm + ar1 < M) av1 = *(const float4*)(A + (size_t)(bm + ar1) * lda + k0 + ak1);
        if (bn + ar0 < N) bv0 = *(const float4*)(Bm + (size_t)(bn + ar0) * ldb + k0 + ak0);
        if (bn + ar1 < N) bv1 = *(const float4*)(Bm + (size_t)(bn + ar1) * ldb + k0 + ak1);
        if (siluA) {
            av0.x = siluf(av0.x); av0.y = siluf(av0.y);
            av0.z = siluf(av0.z); av0.w = siluf(av0.w);
            av1.x = siluf(av1.x); av1.y = siluf(av1.y);
            av1.z = siluf(av1.z); av1.w = siluf(av1.w);
        }
        __syncthreads();
        As[ak0 + 0][ar0] = av0.x; As[ak0 + 1][ar0] = av0.y;
        As[ak0 + 2][ar0] = av0.z; As[ak0 + 3][ar0] = av0.w;
        As[ak1 + 0][ar1] = av1.x; As[ak1 + 1][ar1] = av1.y;
        As[ak1 + 2][ar1] = av1.z; As[ak1 + 3][ar1] = av1.w;
        Bs[ak0 + 0][ar0] = bv0.x; Bs[ak0 + 1][ar0] = bv0.y;
        Bs[ak0 + 2][ar0] = bv0.z; Bs[ak0 + 3][ar0] = bv0.w;
        Bs[ak1 + 0][ar1] = bv1.x; Bs[ak1 + 1][ar1] = bv1.y;
        Bs[ak1 + 2][ar1] = bv1.z; Bs[ak1 + 3][ar1] = bv1.w;
        __syncthreads();
#pragma unroll
        for (int kk = 0; kk < 16; kk++) {
            float a[8], b[8];
            *(float4*)&a[0] = *(const float4*)&As[kk][ty * 8];
            *(float4*)&a[4] = *(const float4*)&As[kk][ty * 8 + 4];
            *(float4*)&b[0] = *(const float4*)&Bs[kk][tx * 8];
            *(float4*)&b[4] = *(const float4*)&Bs[kk][tx * 8 + 4];
#pragma unroll
            for (int i = 0; i < 8; i++)
#pragma unroll
                for (int j = 0; j < 8; j++) acc[i][j] = fmaf(a[i], b[j], acc[i][j]);
        }
    }
#pragma unroll
    for (int i = 0; i < 8; i++) {
        int row = bm + ty * 8 + i;
        if (row >= M) continue;
#pragma unroll
        for (int j = 0; j < 8; j += 4) {
            int col = bn + tx * 8 + j;
            if (col >= N) continue;
            float4 v;
            v.x = acc[i][j + 0] + (bias ? __ldg(bias + col + 0) : 0.0f);
            v.y = acc[i][j + 1] + (bias ? __ldg(bias + col + 1) : 0.0f);
            v.z = acc[i][j + 2] + (bias ? __ldg(bias + col + 2) : 0.0f);
            v.w = acc[i][j + 3] + (bias ? __ldg(bias + col + 3) : 0.0f);
            *(float4*)(C + (size_t)row * ldc + col) = v;
        }
    }
}

// ---------------- fused LN1 + modulate(+store skip) + LN2 (xn tf32-rounded) ----
__global__ __launch_bounds__(256) void ln_mod_kernel(
    const float* __restrict__ x,
    const float* __restrict__ g1, const float* __restrict__ b1,
    const float* __restrict__ g2, const float* __restrict__ b2,
    const float* __restrict__ ada,
    float* __restrict__ skip, float* __restrict__ xn)
{
    __shared__ float sh[8];
    const int row = blockIdx.x;
    const int b = row >> 10;
    const float* xr = x + (size_t)row * Dd;

    float v[4];
#pragma unroll
    for (int j = 0; j < 4; j++) v[j] = xr[threadIdx.x + j * 256];

    float s1 = 0.0f, s2 = 0.0f;
#pragma unroll
    for (int j = 0; j < 4; j++) { s1 += v[j]; s2 += v[j] * v[j]; }
    s1 = blockReduceSum(s1, sh);
    s2 = blockReduceSum(s2, sh);
    float m  = s1 * (1.0f / Dd);
    float rs = rsqrtf(s2 * (1.0f / Dd) - m * m + 1e-5f);

    float t[4];
    s1 = 0.0f; s2 = 0.0f;
#pragma unroll
    for (int j = 0; j < 4; j++) {
        int d = threadIdx.x + j * 256;
        float tt = (v[j] - m) * rs * g1[d] + b1[d];
        tt = tt * (1.0f + ada[b * THREED + Dd + d]) + ada[b * THREED + d];
        t[j] = tt;
        skip[(size_t)row * Dd + d] = tt;
        s1 += tt; s2 += tt * tt;
    }
    s1 = blockReduceSum(s1, sh);
    s2 = blockReduceSum(s2, sh);
    float m2  = s1 * (1.0f / Dd);
    float rs2 = rsqrtf(s2 * (1.0f / Dd) - m2 * m2 + 1e-5f);

#pragma unroll
    for (int j = 0; j < 4; j++) {
        int d = threadIdx.x + j * 256;
        xn[(size_t)row * Dd + d] = roundtf((t[j] - m2) * rs2 * g2[d] + b2[d]);
    }
}

// ---------------- merged selective scans (both branches, one launch) ------------
// One half-warp per (branch, b, e): 16 lanes = 16 SSM states. Branch 1 scans s
// in reverse. Software-pipelined: next step's loads issue before the exp chain.
__global__ __launch_bounds__(256) void scan2_kernel(
    const float* __restrict__ de1, const float* __restrict__ z1,
    const float* __restrict__ dbc1, const float* __restrict__ Alog1,
    const float* __restrict__ Dp1, float* __restrict__ gg1,
    const float* __restrict__ de2, const float* __restrict__ z2,
    const float* __restrict__ dbc2, const float* __restrict__ Alog2,
    const float* __restrict__ Dp2, float* __restrict__ gg2)
{
    const int w    = (blockIdx.x * blockDim.x + threadIdx.x) >> 5;   // 0..4095
    const int lane = threadIdx.x & 31;
    const int half = lane >> 4;
    const int n    = lane & 15;
    const int f    = w * 2 + half;          // 0..8191
    const int br   = f >> 12;               // branch
    const int b    = (f >> 11) & 1;
    const int e    = f & (Ee - 1);

    const float* delta = br ? de2  : de1;
    const float* u     = br ? z2   : z1;
    const float* dbc   = br ? dbc2 : dbc1;
    const float* Alog  = br ? Alog2 : Alog1;
    const float* Dp    = br ? Dp2  : Dp1;
    float*       g     = br ? gg2  : gg1;

    const float A_n  = -__expf(Alog[e * Nn + n]);
    const float Dp_e = Dp[e];

    const int s0 = br ? (Ss - 1) : 0;
    const int dE = br ? -Ee : Ee;
    const int dW = br ? -DBCW : DBCW;
    const float* pD  = delta + (size_t)b * Ss * Ee + (size_t)s0 * Ee + e;
    const float* pU  = u     + (size_t)b * Ss * Ee + (size_t)s0 * Ee + e;
    const float* pBC = dbc   + (size_t)b * Ss * DBCW + (size_t)s0 * DBCW + Rr + n;
    float*       pG  = g     + (size_t)b * Ss * Ee + (size_t)s0 * Ee + e;

    float h = 0.0f;
    float dlt = __ldg(pD), uu = __ldg(pU);
    float Bv = __ldg(pBC), Cv = __ldg(pBC + Nn);

    for (int step = 0; step < Ss - 1; step++) {
        // prefetch next step
        float dlt2 = __ldg(pD + dE);
        float uu2  = __ldg(pU + dE);
        float Bv2  = __ldg(pBC + dW);
        float Cv2  = __ldg(pBC + dW + Nn);

        h = __expf(dlt * A_n) * h + dlt * Bv * uu;
        float y = h * Cv;
        y += __shfl_xor_sync(0xffffffffu, y, 8);
        y += __shfl_xor_sync(0xffffffffu, y, 4);
        y += __shfl_xor_sync(0xffffffffu, y, 2);
        y += __shfl_xor_sync(0xffffffffu, y, 1);
        if (n == 0) *pG = y + uu * Dp_e;

        pD += dE; pU += dE; pBC += dW; pG += dE;
        dlt = dlt2; uu = uu2; Bv = Bv2; Cv = Cv2;
    }
    // final step
    h = __expf(dlt * A_n) * h + dlt * Bv * uu;
    float y = h * Cv;
    y += __shfl_xor_sync(0xffffffffu, y, 8);
    y += __shfl_xor_sync(0xffffffffu, y, 4);
    y += __shfl_xor_sync(0xffffffffu, y, 2);
    y += __shfl_xor_sync(0xffffffffu, y, 1);
    if (n == 0) *pG = y + uu * Dp_e;
}

// ---------------- a = silu(mx) * (g1 + g2), tf32-rounded -------------------------
__global__ void combine_kernel(const float* __restrict__ mx,
                               const float* __restrict__ gg1,
                               const float* __restrict__ gg2,
                               float* __restrict__ a, int n)
{
    int i = blockIdx.x * blockDim.x + threadIdx.x;
    if (i < n) a[i] = roundtf(siluf(mx[i]) * (gg1[i] + gg2[i]));
}

// ---------------- out = x + gate * (tmp + skip) ---------------------------------
__global__ void final_kernel(const float* __restrict__ x,
                             const float* __restrict__ ada,
                             const float* __restrict__ tmp,
                             const float* __restrict__ skip,
                             float* __restrict__ out, int n)
{
    int i = blockIdx.x * blockDim.x + threadIdx.x;
    if (i < n) {
        int row = i >> 10;
        int d   = i & (Dd - 1);
        int b   = row >> 10;
        float gate = ada[b * THREED + 2 * Dd + d];
        out[i] = x[i] + gate * (tmp[i] + skip[i]);
    }
}

// ---------------- host launcher --------------------------------------------------
extern "C" void kernel_launch(void* const* d_in, const int* in_sizes, int n_in,
                              void* d_out, int out_size)
{
    const float* x     = (const float*)d_in[0];
    const float* c     = (const float*)d_in[1];
    const float* n1g   = (const float*)d_in[3];
    const float* n1b   = (const float*)d_in[4];
    const float* n2g   = (const float*)d_in[5];
    const float* n2b   = (const float*)d_in[6];
    const float* Wx    = (const float*)d_in[7];
    const float* bx    = (const float*)d_in[8];
    const float* Wz    = (const float*)d_in[9];
    const float* bz    = (const float*)d_in[10];
    const float* Wf    = (const float*)d_in[11];
    const float* bf    = (const float*)d_in[12];
    const float* Wada  = (const float*)d_in[13];
    const float* bada  = (const float*)d_in[14];
    const float* Wc1   = (const float*)d_in[15];
    const float* bc1   = (const float*)d_in[16];
    const float* Wc2   = (const float*)d_in[17];
    const float* bc2   = (const float*)d_in[18];
    const float* Wdbc1 = (const float*)d_in[19];
    const float* Wdt1  = (const float*)d_in[20];
    const float* bdt1  = (const float*)d_in[21];
    const float* Alog1 = (const float*)d_in[22];
    const float* Dp1   = (const float*)d_in[23];
    const float* Wdbc2 = (const float*)d_in[24];
    const float* Wdt2  = (const float*)d_in[25];
    const float* bdt2  = (const float*)d_in[26];
    const float* Alog2 = (const float*)d_in[27];
    const float* Dp2   = (const float*)d_in[28];
    float* out = (float*)d_out;

    float *ada, *skip, *xn, *mz, *mx, *z1, *z2, *dbc1, *dbc2;
    float *de1, *de2, *gg1, *gg2, *acmb, *tmp, *part;
    float *wz, *wx, *wc1, *wc2, *wdbc1, *wdbc2, *wdt1, *wdt2, *wf;
    cudaGetSymbolAddress((void**)&ada,  g_ada);
    cudaGetSymbolAddress((void**)&skip, g_skip);
    cudaGetSymbolAddress((void**)&xn,   g_xn);
    cudaGetSymbolAddress((void**)&mz,   g_mz);
    cudaGetSymbolAddress((void**)&mx,   g_mx);
    cudaGetSymbolAddress((void**)&z1,   g_z1);
    cudaGetSymbolAddress((void**)&z2,   g_z2);
    cudaGetSymbolAddress((void**)&dbc1, g_dbc1);
    cudaGetSymbolAddress((void**)&dbc2, g_dbc2);
    cudaGetSymbolAddress((void**)&de1,  g_del1);
    cudaGetSymbolAddress((void**)&de2,  g_del2);
    cudaGetSymbolAddress((void**)&gg1,  g_gg1);
    cudaGetSymbolAddress((void**)&gg2,  g_gg2);
    cudaGetSymbolAddress((void**)&acmb, g_acmb);
    cudaGetSymbolAddress((void**)&tmp,  g_tmp);
    cudaGetSymbolAddress((void**)&part, g_part);
    cudaGetSymbolAddress((void**)&wz,    g_wz);
    cudaGetSymbolAddress((void**)&wx,    g_wx);
    cudaGetSymbolAddress((void**)&wc1,   g_wc1);
    cudaGetSymbolAddress((void**)&wc2,   g_wc2);
    cudaGetSymbolAddress((void**)&wdbc1, g_wdbc1);
    cudaGetSymbolAddress((void**)&wdbc2, g_wdbc2);
    cudaGetSymbolAddress((void**)&wdt1,  g_wdt1);
    cudaGetSymbolAddress((void**)&wdt2,  g_wdt2);
    cudaGetSymbolAddress((void**)&wf,    g_wf);

    const int SMEM = 65536;
    cudaFuncSetAttribute(gemm_tf32, cudaFuncAttributeMaxDynamicSharedMemorySize, SMEM);

    // 0. pre-round weights to tf32 (scratch copies)
    auto roundW = [&](const float* src, float* dst, int nElem) {
        int n4 = nElem / 4;
        round_tf32_kernel<<<(n4 + 255) / 256, 256>>>(
            (const float4*)src, (float4*)dst, n4);
    };
    roundW(Wz,    wz,    Ee * Dd);
    roundW(Wx,    wx,    Ee * Dd);
    roundW(Wc1,   wc1,   Ee * Ee);
    roundW(Wc2,   wc2,   Ee * Ee);
    roundW(Wdbc1, wdbc1, DBCW * Ee);
    roundW(Wdbc2, wdbc2, DBCW * Ee);
    roundW(Wdt1,  wdt1,  Ee * Rr);
    roundW(Wdt2,  wdt2,  Ee * Rr);
    roundW(Wf,    wf,    Dd * Ee);

    // 1. ada = silu(c) @ Wada^T + bada   [2, 3072]  (tiny M, fp32 SIMT, fused silu)
    gemm_tn<<<dim3(THREED / 128, 1), 256>>>(c, 2 * Dd, Wada, 2 * Dd, bada,
                                            ada, THREED, Bb, THREED, 2 * Dd, 1);

    // 2. LN1 + modulate (-> skip) + LN2 (-> xn, tf32-rounded)
    ln_mod_kernel<<<BSr, 256>>>(x, n1g, n1b, n2g, n2b, ada, skip, xn);

    // 3/4. mz (rounded), mx  [2048, 2048] K=1024
    gemm_tf32<<<dim3(Ee / 128, BSr / 128, 1), 256, SMEM>>>(
        xn, Dd, wz, Dd, bz, mz, Ee, BSr, Ee, Dd, 2, 0);
    gemm_tf32<<<dim3(Ee / 128, BSr / 128, 1), 256, SMEM>>>(
        xn, Dd, wx, Dd, bx, mx, Ee, BSr, Ee, Dd, 0, 0);

    // 5/6. z1, z2 (rounded)  [2048, 2048] K=2048
    gemm_tf32<<<dim3(Ee / 128, BSr / 128, 1), 256, SMEM>>>(
        mz, Ee, wc1, Ee, bc1, z1, Ee, BSr, Ee, Ee, 2, 0);
    gemm_tf32<<<dim3(Ee / 128, BSr / 128, 1), 256, SMEM>>>(
        mz, Ee, wc2, Ee, bc2, z2, Ee, BSr, Ee, Ee, 2, 0);

    // 7/8. dbc = z @ Wdbc^T  [2048, 96] K=2048  (split-K=8, rounded in reduce)
    gemm_tf32<<<dim3(1, BSr / 128, KSPLIT), 256, SMEM>>>(
        z1, Ee, wdbc1, Ee, nullptr, part, DBCW, BSr, DBCW, Ee, 0, BSr * DBCW);
    reduce_splitk<<<(BSr * DBCW + 255) / 256, 256>>>(part, dbc1, BSr * DBCW);
    gemm_tf32<<<dim3(1, BSr / 128, KSPLIT), 256, SMEM>>>(
        z2, Ee, wdbc2, Ee, nullptr, part, DBCW, BSr, DBCW, Ee, 0, BSr * DBCW);
    reduce_splitk<<<(BSr * DBCW + 255) / 256, 256>>>(part, dbc2, BSr * DBCW);

    // 9/10. delta = softplus(dlt @ Wdt^T + bdt)  [2048, 2048] K=64
    gemm_tf32<<<dim3(Ee / 128, BSr / 128, 1), 256, SMEM>>>(
        dbc1, DBCW, wdt1, Rr, bdt1, de1, Ee, BSr, Ee, Rr, 1, 0);
    gemm_tf32<<<dim3(Ee / 128, BSr / 128, 1), 256, SMEM>>>(
        dbc2, DBCW, wdt2, Rr, bdt2, de2, Ee, BSr, Ee, Rr, 1, 0);

    // 11. both selective scans in one launch (fwd branch 0, bwd branch 1)
    scan2_kernel<<<512, 256>>>(de1, z1, dbc1, Alog1, Dp1, gg1,
                               de2, z2, dbc2, Alog2, Dp2, gg2);

    // 12. acmb = silu(mx) * (gg1 + gg2)  (tf32-rounded)
    combine_kernel<<<(BSr * Ee + 255) / 256, 256>>>(mx, gg1, gg2, acmb, BSr * Ee);

    // 13. tmp = acmb @ Wf^T + bf  [2048, 1024] K=2048
    gemm_tf32<<<dim3(Dd / 128, BSr / 128, 1), 256, SMEM>>>(
        acmb, Ee, wf, Ee, bf, tmp, Dd, BSr, Dd, Ee, 0, 0);

    // 14. out = x + gate * (tmp + skip)
    final_kernel<<<(BSr * Dd + 255) / 256, 256>>>(x, ada, tmp, skip, out, BSr * Dd);
}

// round 7
// speedup vs baseline: 2.8082x; 1.3301x over previous
#include <cuda_runtime.h>
#include <cuda_bf16.h>
#include <math.h>
#include <stdint.h>

// Problem constants
#define Bb   2
#define Ss   1024
#define Dd   1024
#define Ee   2048
#define Nn   16
#define Rr   64
#define BSr  (Bb * Ss)          // 2048 rows
#define DBCW (Rr + 2 * Nn)      // 96
#define THREED (3 * Dd)         // 3072
#define KSPLIT 8
#define SCH  64                 // scan chunk (steps per SMEM stage)
#define NCH  (Ss / SCH)         // 16 chunks

// ---------------- scratch (device globals; no allocation in kernel_launch) ----
__device__ float g_ada  [Bb * THREED];
__device__ float g_skip [BSr * Dd];
__device__ float g_xn   [BSr * Dd];
__device__ float g_mz   [BSr * Ee];
__device__ float g_mx   [BSr * Ee];
__device__ float g_z1   [BSr * Ee];
__device__ float g_z2   [BSr * Ee];
__device__ float g_dbc1 [BSr * DBCW];
__device__ float g_dbc2 [BSr * DBCW];
__device__ float g_del1 [BSr * Ee];
__device__ float g_del2 [BSr * Ee];
__device__ float g_gg1  [BSr * Ee];
__device__ float g_gg2  [BSr * Ee];
__device__ float g_acmb [BSr * Ee];
__device__ float g_tmp  [BSr * Dd];
__device__ float g_part [KSPLIT * BSr * DBCW];

// ---------------- helpers -----------------------------------------------------
__device__ __forceinline__ float siluf(float v) { return v / (1.0f + __expf(-v)); }
__device__ __forceinline__ float softplusf(float v) {
    return (v > 20.0f) ? v : log1pf(__expf(v));
}
__device__ __forceinline__ void mma_tf32(float* c, const uint32_t* a, const uint32_t* b) {
    asm volatile(
        "mma.sync.aligned.m16n8k8.row.col.f32.tf32.tf32.f32 "
        "{%0,%1,%2,%3},{%4,%5,%6,%7},{%8,%9},{%0,%1,%2,%3};"
        : "+f"(c[0]), "+f"(c[1]), "+f"(c[2]), "+f"(c[3])
        : "r"(a[0]), "r"(a[1]), "r"(a[2]), "r"(a[3]), "r"(b[0]), "r"(b[1]));
}
#define CP16(dst, src, sz) \
    asm volatile("cp.async.cg.shared.global [%0], [%1], 16, %2;" \
                 :: "r"(dst), "l"(src), "r"(sz))
#define CP16F(dst, src) \
    asm volatile("cp.async.cg.shared.global [%0], [%1], 16;" \
                 :: "r"(dst), "l"(src))

__device__ __forceinline__ float blockReduceSum(float v, float* sh) {
    int lane = threadIdx.x & 31, wid = threadIdx.x >> 5;
#pragma unroll
    for (int o = 16; o; o >>= 1) v += __shfl_xor_sync(0xffffffffu, v, o);
    __syncthreads();
    if (lane == 0) sh[wid] = v;
    __syncthreads();
    if (wid == 0) {
        v = (lane < 8) ? sh[lane] : 0.0f;
#pragma unroll
        for (int o = 4; o; o >>= 1) v += __shfl_xor_sync(0xffffffffu, v, o);
        if (lane == 0) sh[0] = v;
    }
    __syncthreads();
    return sh[0];
}

// ---------------- tf32 tensor-core GEMM (cp.async, HW-truncated fp32 inputs) ----
// C[M,N] = A[M,K] * W[N,K]^T (+bias, +epi). Tile 128x128x32, 256 threads,
// 8 warps (2x4), warp tile 64x32, mma m16n8k8 tf32. 2-stage cp.async pipeline,
// XOR-swizzled SMEM. fp32 inputs fed raw to mma (HW keeps top 10 mantissa bits).
// epi: 0 none, 1 softplus.
// gridDim.z = split-K; each z writes C + z*partStride (bias only if gridDim.z==1).
__global__ __launch_bounds__(256, 2) void gemm_tf32(
    const float* __restrict__ A, int lda,
    const float* __restrict__ W, int ldb,
    const float* __restrict__ bias,
    float* __restrict__ C, int ldc,
    int M, int N, int K, int epi, int partStride)
{
    extern __shared__ float smf[];
    float* As = smf;            // [2][128*32]
    float* Bs = smf + 8192;     // [2][128*32]

    const int tid  = threadIdx.x;
    const int wid  = tid >> 5, lane = tid & 31;
    const int wm   = wid >> 2, wn = wid & 3;
    const int grp  = lane >> 2, tig = lane & 3;
    const int bm   = blockIdx.y * 128, bn = blockIdx.x * 128;
    const int klen   = K / gridDim.z;
    const int kstart = blockIdx.z * klen;
    const int ntile  = klen >> 5;

    float acc[4][4][4];
#pragma unroll
    for (int i = 0; i < 4; i++)
#pragma unroll
        for (int j = 0; j < 4; j++)
#pragma unroll
            for (int r = 0; r < 4; r++) acc[i][j][r] = 0.0f;

    uint32_t aSm[4], bSm[4], bSz[4];
    const float* aP[4];
    const float* bP[4];
    const uint32_t sA = (uint32_t)__cvta_generic_to_shared(As);
    const uint32_t sB = (uint32_t)__cvta_generic_to_shared(Bs);
#pragma unroll
    for (int i = 0; i < 4; i++) {
        int f = tid + i * 256;
        int m = f >> 3, kq = (f & 7) * 4;
        int col = kq ^ ((m & 7) << 2);
        aSm[i] = sA + (uint32_t)(m * 32 + col) * 4u;
        bSm[i] = sB + (uint32_t)(m * 32 + col) * 4u;
        aP[i]  = A + (size_t)(bm + m) * lda + kstart + kq;
        int brow = bn + m;
        bSz[i] = (brow < N) ? 16u : 0u;
        if (brow >= N) brow = N - 1;
        bP[i]  = W + (size_t)brow * ldb + kstart + kq;
    }

#pragma unroll
    for (int i = 0; i < 4; i++) {
        CP16(aSm[i], aP[i], 16u);
        CP16(bSm[i], bP[i], bSz[i]);
        aP[i] += 32; bP[i] += 32;
    }
    asm volatile("cp.async.commit_group;");

    const int swz = grp << 2;

    for (int t = 0; t < ntile; t++) {
        if (t + 1 < ntile) {
            const uint32_t so = (uint32_t)(((t + 1) & 1) * 16384);
#pragma unroll
            for (int i = 0; i < 4; i++) {
                CP16(aSm[i] + so, aP[i], 16u);
                CP16(bSm[i] + so, bP[i], bSz[i]);
                aP[i] += 32; bP[i] += 32;
            }
            asm volatile("cp.async.commit_group;");
            asm volatile("cp.async.wait_group 1;");
        } else {
            asm volatile("cp.async.wait_group 0;");
        }
        __syncthreads();

        const int buf = (t & 1) * 4096;
#pragma unroll
        for (int ks = 0; ks < 4; ks++) {
            const int kb = ks * 8;
            const int c0 = (kb + tig) ^ swz;
            const int c1 = (kb + tig + 4) ^ swz;
            uint32_t af[4][4], bf[4][2];
#pragma unroll
            for (int mt = 0; mt < 4; mt++) {
                int r0 = (wm * 64 + mt * 16 + grp) * 32;
                af[mt][0] = __float_as_uint(As[buf + r0 + c0]);
                af[mt][1] = __float_as_uint(As[buf + r0 + 256 + c0]);
                af[mt][2] = __float_as_uint(As[buf + r0 + c1]);
                af[mt][3] = __float_as_uint(As[buf + r0 + 256 + c1]);
            }
#pragma unroll
            for (int nt = 0; nt < 4; nt++) {
                int r0 = (wn * 32 + nt * 8 + grp) * 32;
                bf[nt][0] = __float_as_uint(Bs[buf + r0 + c0]);
                bf[nt][1] = __float_as_uint(Bs[buf + r0 + c1]);
            }
#pragma unroll
            for (int mt = 0; mt < 4; mt++)
#pragma unroll
                for (int nt = 0; nt < 4; nt++)
                    mma_tf32(acc[mt][nt], af[mt], bf[nt]);
        }
        __syncthreads();
    }

    float* Cp = C + (size_t)blockIdx.z * partStride;
    const bool doBias = (bias != nullptr) && (gridDim.z == 1);
#pragma unroll
    for (int mt = 0; mt < 4; mt++) {
#pragma unroll
        for (int nt = 0; nt < 4; nt++) {
            int row = bm + wm * 64 + mt * 16 + grp;
            int col = bn + wn * 32 + nt * 8 + tig * 2;
            if (col >= N) continue;
            float b0 = doBias ? __ldg(bias + col) : 0.0f;
            float b1 = doBias ? __ldg(bias + col + 1) : 0.0f;
            float v0 = acc[mt][nt][0] + b0, v1 = acc[mt][nt][1] + b1;
            float v2 = acc[mt][nt][2] + b0, v3 = acc[mt][nt][3] + b1;
            if (epi == 1) {
                v0 = softplusf(v0); v1 = softplusf(v1);
                v2 = softplusf(v2); v3 = softplusf(v3);
            }
            float2 lo = make_float2(v0, v1), hi = make_float2(v2, v3);
            *(float2*)&Cp[(size_t)row * ldc + col] = lo;
            *(float2*)&Cp[(size_t)(row + 8) * ldc + col] = hi;
        }
    }
}

// ---------------- split-K reduction ---------------------------------------------
__global__ void reduce_splitk(const float* __restrict__ part,
                              float* __restrict__ out, int n)
{
    int i = blockIdx.x * blockDim.x + threadIdx.x;
    if (i < n) {
        float s = 0.0f;
#pragma unroll
        for (int z = 0; z < KSPLIT; z++) s += part[(size_t)z * n + i];
        out[i] = s;
    }
}

// ---------------- small fp32 GEMM for ada (M=2), fused silu on A ----------------
__global__ __launch_bounds__(256) void gemm_tn(
    const float* __restrict__ A, int lda,
    const float* __restrict__ Bm, int ldb,
    const float* __restrict__ bias,
    float* __restrict__ C, int ldc,
    int M, int N, int K, int siluA)
{
    __shared__ float As[16][128];
    __shared__ float Bs[16][128];
    const int bm = blockIdx.y * 128;
    const int bn = blockIdx.x * 128;
    const int tid = threadIdx.x;
    const int tx = tid & 15;
    const int ty = tid >> 4;

    float acc[8][8];
#pragma unroll
    for (int i = 0; i < 8; i++)
#pragma unroll
        for (int j = 0; j < 8; j++) acc[i][j] = 0.0f;

    const int ar0 = tid >> 2, ak0 = (tid & 3) * 4;
    const int l1 = tid + 256;
    const int ar1 = l1 >> 2, ak1 = (l1 & 3) * 4;

    for (int k0 = 0; k0 < K; k0 += 16) {
        float4 av0 = make_float4(0, 0, 0, 0), av1 = av0, bv0 = av0, bv1 = av0;
        if (bm + ar0 < M) av0 = *(const float4*)(A + (size_t)(bm + ar0) * lda + k0 + ak0);
        if (bm + ar1 < M) av1 = *(const float4*)(A + (size_t)(bm + ar1) * lda + k0 + ak1);
        if (bn + ar0 < N) bv0 = *(const float4*)(Bm + (size_t)(bn + ar0) * ldb + k0 + ak0);
        if (bn + ar1 < N) bv1 = *(const float4*)(Bm + (size_t)(bn + ar1) * ldb + k0 + ak1);
        if (siluA) {
            av0.x = siluf(av0.x); av0.y = siluf(av0.y);
            av0.z = siluf(av0.z); av0.w = siluf(av0.w);
            av1.x = siluf(av1.x); av1.y = siluf(av1.y);
            av1.z = siluf(av1.z); av1.w = siluf(av1.w);
        }
        __syncthreads();
        As[ak0 + 0][ar0] = av0.x; As[ak0 + 1][ar0] = av0.y;
        As[ak0 + 2][ar0] = av0.z; As[ak0 + 3][ar0] = av0.w;
        As[ak1 + 0][ar1] = av1.x; As[ak1 + 1][ar1] = av1.y;
        As[ak1 + 2][ar1] = av1.z; As[ak1 + 3][ar1] = av1.w;
        Bs[ak0 + 0][ar0] = bv0.x; Bs[ak0 + 1][ar0] = bv0.y;
        Bs[ak0 + 2][ar0] = bv0.z; Bs[ak0 + 3][ar0] = bv0.w;
        Bs[ak1 + 0][ar1] = bv1.x; Bs[ak1 + 1][ar1] = bv1.y;
        Bs[ak1 + 2][ar1] = bv1.z; Bs[ak1 + 3][ar1] = bv1.w;
        __syncthreads();
#pragma unroll
        for (int kk = 0; kk < 16; kk++) {
            float a[8], b[8];
            *(float4*)&a[0] = *(const float4*)&As[kk][ty * 8];
            *(float4*)&a[4] = *(const float4*)&As[kk][ty * 8 + 4];
            *(float4*)&b[0] = *(const float4*)&Bs[kk][tx * 8];
            *(float4*)&b[4] = *(const float4*)&Bs[kk][tx * 8 + 4];
#pragma unroll
            for (int i = 0; i < 8; i++)
#pragma unroll
                for (int j = 0; j < 8; j++) acc[i][j] = fmaf(a[i], b[j], acc[i][j]);
        }
    }
#pragma unroll
    for (int i = 0; i < 8; i++) {
        int row = bm + ty * 8 + i;
        if (row >= M) continue;
#pragma unroll
        for (int j = 0; j < 8; j += 4) {
            int col = bn + tx * 8 + j;
            if (col >= N) continue;
            float4 v;
            v.x = acc[i][j + 0] + (bias ? __ldg(bias + col + 0) : 0.0f);
            v.y = acc[i][j + 1] + (bias ? __ldg(bias + col + 1) : 0.0f);
            v.z = acc[i][j + 2] + (bias ? __ldg(bias + col + 2) : 0.0f);
            v.w = acc[i][j + 3] + (bias ? __ldg(bias + col + 3) : 0.0f);
            *(float4*)(C + (size_t)row * ldc + col) = v;
        }
    }
}

// ---------------- fused LN1 + modulate(+store skip) + LN2 -----------------------
__global__ __launch_bounds__(256) void ln_mod_kernel(
    const float* __restrict__ x,
    const float* __restrict__ g1, const float* __restrict__ b1,
    const float* __restrict__ g2, const float* __restrict__ b2,
    const float* __restrict__ ada,
    float* __restrict__ skip, float* __restrict__ xn)
{
    __shared__ float sh[8];
    const int row = blockIdx.x;
    const int b = row >> 10;
    const float* xr = x + (size_t)row * Dd;

    float v[4];
#pragma unroll
    for (int j = 0; j < 4; j++) v[j] = xr[threadIdx.x + j * 256];

    float s1 = 0.0f, s2 = 0.0f;
#pragma unroll
    for (int j = 0; j < 4; j++) { s1 += v[j]; s2 += v[j] * v[j]; }
    s1 = blockReduceSum(s1, sh);
    s2 = blockReduceSum(s2, sh);
    float m  = s1 * (1.0f / Dd);
    float rs = rsqrtf(s2 * (1.0f / Dd) - m * m + 1e-5f);

    float t[4];
    s1 = 0.0f; s2 = 0.0f;
#pragma unroll
    for (int j = 0; j < 4; j++) {
        int d = threadIdx.x + j * 256;
        float tt = (v[j] - m) * rs * g1[d] + b1[d];
        tt = tt * (1.0f + ada[b * THREED + Dd + d]) + ada[b * THREED + d];
        t[j] = tt;
        skip[(size_t)row * Dd + d] = tt;
        s1 += tt; s2 += tt * tt;
    }
    s1 = blockReduceSum(s1, sh);
    s2 = blockReduceSum(s2, sh);
    float m2  = s1 * (1.0f / Dd);
    float rs2 = rsqrtf(s2 * (1.0f / Dd) - m2 * m2 + 1e-5f);

#pragma unroll
    for (int j = 0; j < 4; j++) {
        int d = threadIdx.x + j * 256;
        xn[(size_t)row * Dd + d] = (t[j] - m2) * rs2 * g2[d] + b2[d];
    }
}

// ---------------- SMEM-staged selective scan -------------------------------------
// Block = 16 consecutive e for one (branch, b). 256 threads = 16 half-warp units
// (unit u = tid/16 -> e = e0+u; lane n = tid%15 -> SSM state). Chunks of SCH=64
// steps double-buffered via cp.async; gg staged in SMEM, flushed coalesced.
// Branch 1 scans s in reverse (flip/scan/flip == reverse scan).
__global__ __launch_bounds__(256) void scan_smem_kernel(
    const float* __restrict__ de1, const float* __restrict__ z1,
    const float* __restrict__ dbc1, const float* __restrict__ Alog1,
    const float* __restrict__ Dp1, float* __restrict__ gg1,
    const float* __restrict__ de2, const float* __restrict__ z2,
    const float* __restrict__ dbc2, const float* __restrict__ Alog2,
    const float* __restrict__ Dp2, float* __restrict__ gg2)
{
    __shared__ float deS[2][SCH][16];
    __shared__ float zS [2][SCH][16];
    __shared__ float bcS[2][SCH][32];
    __shared__ float ggS[SCH][16];

    const int tid = threadIdx.x;
    const int u   = tid >> 4;          // 0..15  (e unit)
    const int n   = tid & 15;          // 0..15  (SSM state)

    const int bx = blockIdx.x;         // 0..511
    const int et = bx & 127;
    const int b  = (bx >> 7) & 1;
    const int br = bx >> 8;
    const int e0 = et * 16;

    const float* de   = br ? de2  : de1;
    const float* z    = br ? z2   : z1;
    const float* dbc  = br ? dbc2 : dbc1;
    const float* Alog = br ? Alog2 : Alog1;
    const float* Dp   = br ? Dp2  : Dp1;
    float*       gg   = br ? gg2  : gg1;

    const int e = e0 + u;
    const float A_n  = -__expf(Alog[e * Nn + n]);
    const float Dp_e = Dp[e];

    const size_t rowBase = (size_t)b * Ss;   // row index base

    // cp.async targets
    uint32_t deSm = (uint32_t)__cvta_generic_to_shared(&deS[0][0][0]);
    uint32_t zSm  = (uint32_t)__cvta_generic_to_shared(&zS[0][0][0]);
    uint32_t bcSm = (uint32_t)__cvta_generic_to_shared(&bcS[0][0][0]);

    // per-thread load roles
    const int lr  = tid >> 2;          // de/z row 0..63
    const int lp  = (tid & 3) * 4;     // de/z col part
    const int br0 = (tid * 2) >> 3;    // bc rows (2 per thread)
    const int bp0 = ((tid * 2) & 7) * 4;
    const int br1 = (tid * 2 + 1) >> 3;
    const int bp1 = ((tid * 2 + 1) & 7) * 4;

    auto loadChunk = [&](int c, int buf) {
        // de / z rows: 64 rows x 64B
        int s = br ? (Ss - 1 - (c * SCH + lr)) : (c * SCH + lr);
        const float* gd = de + (rowBase + s) * Ee + e0 + lp;
        const float* gz = z  + (rowBase + s) * Ee + e0 + lp;
        CP16F(deSm + (uint32_t)((buf * SCH + lr) * 16 + lp) * 4u, gd);
        CP16F(zSm  + (uint32_t)((buf * SCH + lr) * 16 + lp) * 4u, gz);
        // bc rows: 64 rows x 128B (B|C), 2 transfers per thread
        int s0 = br ? (Ss - 1 - (c * SCH + br0)) : (c * SCH + br0);
        int s1b = br ? (Ss - 1 - (c * SCH + br1)) : (c * SCH + br1);
        const float* g0 = dbc + (rowBase + s0) * DBCW + Rr + bp0;
        const float* g1 = dbc + (rowBase + s1b) * DBCW + Rr + bp1;
        CP16F(bcSm + (uint32_t)((buf * SCH + br0) * 32 + bp0) * 4u, g0);
        CP16F(bcSm + (uint32_t)((buf * SCH + br1) * 32 + bp1) * 4u, g1);
    };

    loadChunk(0, 0);
    asm volatile("cp.async.commit_group;");

    float h = 0.0f;

    for (int c = 0; c < NCH; c++) {
        if (c + 1 < NCH) {
            loadChunk(c + 1, (c + 1) & 1);
            asm volatile("cp.async.commit_group;");
            asm volatile("cp.async.wait_group 1;");
        } else {
            asm volatile("cp.async.wait_group 0;");
        }
        __syncthreads();

        const int buf = c & 1;
#pragma unroll 4
        for (int cs = 0; cs < SCH; cs++) {
            float dlt = deS[buf][cs][u];
            float uu  = zS[buf][cs][u];
            float Bv  = bcS[buf][cs][n];
            float Cv  = bcS[buf][cs][16 + n];

            h = __expf(dlt * A_n) * h + dlt * Bv * uu;
            float y = h * Cv;
            y += __shfl_xor_sync(0xffffffffu, y, 8);
            y += __shfl_xor_sync(0xffffffffu, y, 4);
            y += __shfl_xor_sync(0xffffffffu, y, 2);
            y += __shfl_xor_sync(0xffffffffu, y, 1);
            if (n == 0) ggS[cs][u] = y + uu * Dp_e;
        }
        __syncthreads();

        // flush ggS: thread t writes float4 at row t/4, cols (t%4)*4
        {
            int r = tid >> 2, p = (tid & 3) * 4;
            int s = br ? (Ss - 1 - (c * SCH + r)) : (c * SCH + r);
            *(float4*)&gg[(rowBase + s) * Ee + e0 + p] = *(float4*)&ggS[r][p];
        }
    }
}

// ---------------- a = silu(mx) * (g1 + g2) ---------------------------------------
__global__ void combine_kernel(const float4* __restrict__ mx,
                               const float4* __restrict__ gg1,
                               const float4* __restrict__ gg2,
                               float4* __restrict__ a, int n4)
{
    int i = blockIdx.x * blockDim.x + threadIdx.x;
    if (i < n4) {
        float4 m = mx[i], p = gg1[i], q = gg2[i], r;
        r.x = siluf(m.x) * (p.x + q.x);
        r.y = siluf(m.y) * (p.y + q.y);
        r.z = siluf(m.z) * (p.z + q.z);
        r.w = siluf(m.w) * (p.w + q.w);
        a[i] = r;
    }
}

// ---------------- out = x + gate * (tmp + skip) ----------------------------------
__global__ void final_kernel(const float4* __restrict__ x,
                             const float* __restrict__ ada,
                             const float4* __restrict__ tmp,
                             const float4* __restrict__ skip,
                             float4* __restrict__ out, int n4)
{
    int i = blockIdx.x * blockDim.x + threadIdx.x;
    if (i < n4) {
        int d4  = i & (Dd / 4 - 1);
        int b   = i >> 18;               // i / (S*D/4)
        const float4 g = *(const float4*)&ada[b * THREED + 2 * Dd + d4 * 4];
        float4 xv = x[i], tv = tmp[i], sv = skip[i], o;
        o.x = xv.x + g.x * (tv.x + sv.x);
        o.y = xv.y + g.y * (tv.y + sv.y);
        o.z = xv.z + g.z * (tv.z + sv.z);
        o.w = xv.w + g.w * (tv.w + sv.w);
        out[i] = o;
    }
}

// ---------------- host launcher ----------------------------------------------------
extern "C" void kernel_launch(void* const* d_in, const int* in_sizes, int n_in,
                              void* d_out, int out_size)
{
    const float* x     = (const float*)d_in[0];
    const float* c     = (const float*)d_in[1];
    const float* n1g   = (const float*)d_in[3];
    const float* n1b   = (const float*)d_in[4];
    const float* n2g   = (const float*)d_in[5];
    const float* n2b   = (const float*)d_in[6];
    const float* Wx    = (const float*)d_in[7];
    const float* bx    = (const float*)d_in[8];
    const float* Wz    = (const float*)d_in[9];
    const float* bz    = (const float*)d_in[10];
    const float* Wf    = (const float*)d_in[11];
    const float* bf    = (const float*)d_in[12];
    const float* Wada  = (const float*)d_in[13];
    const float* bada  = (const float*)d_in[14];
    const float* Wc1   = (const float*)d_in[15];
    const float* bc1   = (const float*)d_in[16];
    const float* Wc2   = (const float*)d_in[17];
    const float* bc2   = (const float*)d_in[18];
    const float* Wdbc1 = (const float*)d_in[19];
    const float* Wdt1  = (const float*)d_in[20];
    const float* bdt1  = (const float*)d_in[21];
    const float* Alog1 = (const float*)d_in[22];
    const float* Dp1   = (const float*)d_in[23];
    const float* Wdbc2 = (const float*)d_in[24];
    const float* Wdt2  = (const float*)d_in[25];
    const float* bdt2  = (const float*)d_in[26];
    const float* Alog2 = (const float*)d_in[27];
    const float* Dp2   = (const float*)d_in[28];
    float* out = (float*)d_out;

    float *ada, *skip, *xn, *mz, *mx, *z1, *z2, *dbc1, *dbc2;
    float *de1, *de2, *gg1, *gg2, *acmb, *tmp, *part;
    cudaGetSymbolAddress((void**)&ada,  g_ada);
    cudaGetSymbolAddress((void**)&skip, g_skip);
    cudaGetSymbolAddress((void**)&xn,   g_xn);
    cudaGetSymbolAddress((void**)&mz,   g_mz);
    cudaGetSymbolAddress((void**)&mx,   g_mx);
    cudaGetSymbolAddress((void**)&z1,   g_z1);
    cudaGetSymbolAddress((void**)&z2,   g_z2);
    cudaGetSymbolAddress((void**)&dbc1, g_dbc1);
    cudaGetSymbolAddress((void**)&dbc2, g_dbc2);
    cudaGetSymbolAddress((void**)&de1,  g_del1);
    cudaGetSymbolAddress((void**)&de2,  g_del2);
    cudaGetSymbolAddress((void**)&gg1,  g_gg1);
    cudaGetSymbolAddress((void**)&gg2,  g_gg2);
    cudaGetSymbolAddress((void**)&acmb, g_acmb);
    cudaGetSymbolAddress((void**)&tmp,  g_tmp);
    cudaGetSymbolAddress((void**)&part, g_part);

    const int SMEM = 65536;
    cudaFuncSetAttribute(gemm_tf32, cudaFuncAttributeMaxDynamicSharedMemorySize, SMEM);

    // 1. ada = silu(c) @ Wada^T + bada   [2, 3072]  (tiny M, fp32 SIMT, fused silu)
    gemm_tn<<<dim3(THREED / 128, 1), 256>>>(c, 2 * Dd, Wada, 2 * Dd, bada,
                                            ada, THREED, Bb, THREED, 2 * Dd, 1);

    // 2. LN1 + modulate (-> skip) + LN2 (-> xn)
    ln_mod_kernel<<<BSr, 256>>>(x, n1g, n1b, n2g, n2b, ada, skip, xn);

    // 3/4. mz, mx  [2048, 2048] K=1024
    gemm_tf32<<<dim3(Ee / 128, BSr / 128, 1), 256, SMEM>>>(
        xn, Dd, Wz, Dd, bz, mz, Ee, BSr, Ee, Dd, 0, 0);
    gemm_tf32<<<dim3(Ee / 128, BSr / 128, 1), 256, SMEM>>>(
        xn, Dd, Wx, Dd, bx, mx, Ee, BSr, Ee, Dd, 0, 0);

    // 5/6. z1, z2  [2048, 2048] K=2048
    gemm_tf32<<<dim3(Ee / 128, BSr / 128, 1), 256, SMEM>>>(
        mz, Ee, Wc1, Ee, bc1, z1, Ee, BSr, Ee, Ee, 0, 0);
    gemm_tf32<<<dim3(Ee / 128, BSr / 128, 1), 256, SMEM>>>(
        mz, Ee, Wc2, Ee, bc2, z2, Ee, BSr, Ee, Ee, 0, 0);

    // 7/8. dbc = z @ Wdbc^T  [2048, 96] K=2048  (split-K=8)
    gemm_tf32<<<dim3(1, BSr / 128, KSPLIT), 256, SMEM>>>(
        z1, Ee, Wdbc1, Ee, nullptr, part, DBCW, BSr, DBCW, Ee, 0, BSr * DBCW);
    reduce_splitk<<<(BSr * DBCW + 255) / 256, 256>>>(part, dbc1, BSr * DBCW);
    gemm_tf32<<<dim3(1, BSr / 128, KSPLIT), 256, SMEM>>>(
        z2, Ee, Wdbc2, Ee, nullptr, part, DBCW, BSr, DBCW, Ee, 0, BSr * DBCW);
    reduce_splitk<<<(BSr * DBCW + 255) / 256, 256>>>(part, dbc2, BSr * DBCW);

    // 9/10. delta = softplus(dlt @ Wdt^T + bdt)  [2048, 2048] K=64
    gemm_tf32<<<dim3(Ee / 128, BSr / 128, 1), 256, SMEM>>>(
        dbc1, DBCW, Wdt1, Rr, bdt1, de1, Ee, BSr, Ee, Rr, 1, 0);
    gemm_tf32<<<dim3(Ee / 128, BSr / 128, 1), 256, SMEM>>>(
        dbc2, DBCW, Wdt2, Rr, bdt2, de2, Ee, BSr, Ee, Rr, 1, 0);

    // 11. both selective scans, SMEM-staged (fwd branch 0, bwd branch 1)
    scan_smem_kernel<<<512, 256>>>(de1, z1, dbc1, Alog1, Dp1, gg1,
                                   de2, z2, dbc2, Alog2, Dp2, gg2);

    // 12. acmb = silu(mx) * (gg1 + gg2)
    combine_kernel<<<(BSr * Ee / 4 + 255) / 256, 256>>>(
        (const float4*)mx, (const float4*)gg1, (const float4*)gg2,
        (float4*)acmb, BSr * Ee / 4);

    // 13. tmp = acmb @ Wf^T + bf  [2048, 1024] K=2048
    gemm_tf32<<<dim3(Dd / 128, BSr / 128, 1), 256, SMEM>>>(
        acmb, Ee, Wf, Ee, bf, tmp, Dd, BSr, Dd, Ee, 0, 0);

    // 14. out = x + gate * (tmp + skip)
    final_kernel<<<(BSr * Dd / 4 + 255) / 256, 256>>>(
        (const float4*)x, ada, (const float4*)tmp, (const float4*)skip,
        (float4*)out, BSr * Dd / 4);
}

// round 8
// speedup vs baseline: 4.4168x; 1.5728x over previous
#include <cuda_runtime.h>
#include <cuda_bf16.h>
#include <math.h>
#include <stdint.h>

// Problem constants
#define Bb   2
#define Ss   1024
#define Dd   1024
#define Ee   2048
#define Nn   16
#define Rr   64
#define BSr  (Bb * Ss)          // 2048 rows
#define DBCW (Rr + 2 * Nn)      // 96
#define THREED (3 * Dd)         // 3072
#define KSPLIT 8
#define SCH  64                 // scan chunk (steps per SMEM stage)
#define NCH  (Ss / SCH)         // 16 chunks

// ---------------- scratch (device globals; no allocation in kernel_launch) ----
__device__ float g_ada  [Bb * THREED];
__device__ float g_skip [BSr * Dd];
__device__ float g_xn   [BSr * Dd];
__device__ float g_mzx  [BSr * 2 * Ee];      // mz | mx  (ld = 4096)
__device__ float g_z12  [BSr * 2 * Ee];      // z1 | z2  (ld = 4096)
__device__ float g_dbc1 [BSr * DBCW];
__device__ float g_dbc2 [BSr * DBCW];
__device__ float g_del1 [BSr * Ee];
__device__ float g_del2 [BSr * Ee];
__device__ float g_gg1  [BSr * Ee];
__device__ float g_gg2  [BSr * Ee];
__device__ float g_acmb [BSr * Ee];
__device__ float g_tmp  [BSr * Dd];
__device__ float g_part [KSPLIT * BSr * DBCW];
// pre-rounded (tf32) weights / concat biases
__device__ float g_wzx  [2 * Ee * Dd];       // [Wz ; Wx] rounded
__device__ float g_wc12 [2 * Ee * Ee];       // [Wc1 ; Wc2] rounded
__device__ float g_wdbc1[DBCW * Ee];
__device__ float g_wdbc2[DBCW * Ee];
__device__ float g_wdt1 [Ee * Rr];
__device__ float g_wdt2 [Ee * Rr];
__device__ float g_wf   [Dd * Ee];
__device__ float g_bzx  [2 * Ee];            // [bz ; bx]
__device__ float g_bc12 [2 * Ee];            // [bc1 ; bc2]

// ---------------- helpers -----------------------------------------------------
__device__ __forceinline__ float siluf(float v) { return v / (1.0f + __expf(-v)); }
__device__ __forceinline__ float softplusf(float v) {
    return (v > 20.0f) ? v : log1pf(__expf(v));
}
__device__ __forceinline__ uint32_t f2tf32(float f) {
    uint32_t u;
    asm("cvt.rna.tf32.f32 %0, %1;" : "=r"(u) : "f"(f));
    return u;
}
__device__ __forceinline__ float roundtf(float f) {
    return __uint_as_float(f2tf32(f));
}
__device__ __forceinline__ void mma_tf32(float* c, const uint32_t* a, const uint32_t* b) {
    asm volatile(
        "mma.sync.aligned.m16n8k8.row.col.f32.tf32.tf32.f32 "
        "{%0,%1,%2,%3},{%4,%5,%6,%7},{%8,%9},{%0,%1,%2,%3};"
        : "+f"(c[0]), "+f"(c[1]), "+f"(c[2]), "+f"(c[3])
        : "r"(a[0]), "r"(a[1]), "r"(a[2]), "r"(a[3]), "r"(b[0]), "r"(b[1]));
}
#define CP16(dst, src, sz) \
    asm volatile("cp.async.cg.shared.global [%0], [%1], 16, %2;" \
                 :: "r"(dst), "l"(src), "r"(sz))
#define CP16F(dst, src) \
    asm volatile("cp.async.cg.shared.global [%0], [%1], 16;" \
                 :: "r"(dst), "l"(src))

__device__ __forceinline__ float blockReduceSum(float v, float* sh) {
    int lane = threadIdx.x & 31, wid = threadIdx.x >> 5;
#pragma unroll
    for (int o = 16; o; o >>= 1) v += __shfl_xor_sync(0xffffffffu, v, o);
    __syncthreads();
    if (lane == 0) sh[wid] = v;
    __syncthreads();
    if (wid == 0) {
        v = (lane < 8) ? sh[lane] : 0.0f;
#pragma unroll
        for (int o = 4; o; o >>= 1) v += __shfl_xor_sync(0xffffffffu, v, o);
        if (lane == 0) sh[0] = v;
    }
    __syncthreads();
    return sh[0];
}

// ---------------- weight pre-round to tf32 --------------------------------------
__global__ void round_tf32_kernel(const float4* __restrict__ in,
                                  float4* __restrict__ out, int n4)
{
    int i = blockIdx.x * blockDim.x + threadIdx.x;
    if (i < n4) {
        float4 v = in[i];
        v.x = roundtf(v.x); v.y = roundtf(v.y);
        v.z = roundtf(v.z); v.w = roundtf(v.w);
        out[i] = v;
    }
}

// ---------------- concat two vectors --------------------------------------------
__global__ void concat2_kernel(const float* __restrict__ a,
                               const float* __restrict__ b,
                               float* __restrict__ out, int n)
{
    int i = blockIdx.x * blockDim.x + threadIdx.x;
    if (i < 2 * n) out[i] = (i < n) ? a[i] : b[i - n];
}

// ---------------- tf32 tensor-core GEMM (3-stage cp.async) ----------------------
// C[M,N] = A[M,K] * W[N,K]^T (+bias, +epi). Tile 128x128x32, 256 threads,
// 8 warps (2x4), warp tile 64x32, mma m16n8k8 tf32. 3-stage cp.async pipeline,
// XOR-swizzled SMEM. Inputs must be tf32-pre-rounded (HW truncation is a no-op).
// epi: 0 none, 1 softplus. nRound: columns [0,nRound) get rna-rounded on store.
// gridDim.z = split-K; each z writes C + z*partStride (bias only if gridDim.z==1).
__global__ __launch_bounds__(256, 2) void gemm_tf32(
    const float* __restrict__ A, int lda,
    const float* __restrict__ W, int ldb,
    const float* __restrict__ bias,
    float* __restrict__ C, int ldc,
    int M, int N, int K, int epi, int nRound, int partStride)
{
    extern __shared__ float smf[];
    float* As = smf;             // [3][128*32]
    float* Bs = smf + 12288;     // [3][128*32]

    const int tid  = threadIdx.x;
    const int wid  = tid >> 5, lane = tid & 31;
    const int wm   = wid >> 2, wn = wid & 3;
    const int grp  = lane >> 2, tig = lane & 3;
    const int bm   = blockIdx.y * 128, bn = blockIdx.x * 128;
    const int klen   = K / gridDim.z;
    const int kstart = blockIdx.z * klen;
    const int ntile  = klen >> 5;

    float acc[4][4][4];
#pragma unroll
    for (int i = 0; i < 4; i++)
#pragma unroll
        for (int j = 0; j < 4; j++)
#pragma unroll
            for (int r = 0; r < 4; r++) acc[i][j][r] = 0.0f;

    uint32_t aSm[4], bSm[4], bSz[4];
    const float* aP[4];
    const float* bP[4];
    const uint32_t sA = (uint32_t)__cvta_generic_to_shared(As);
    const uint32_t sB = (uint32_t)__cvta_generic_to_shared(Bs);
#pragma unroll
    for (int i = 0; i < 4; i++) {
        int f = tid + i * 256;
        int m = f >> 3, kq = (f & 7) * 4;
        int col = kq ^ ((m & 7) << 2);
        aSm[i] = sA + (uint32_t)(m * 32 + col) * 4u;
        bSm[i] = sB + (uint32_t)(m * 32 + col) * 4u;
        aP[i]  = A + (size_t)(bm + m) * lda + kstart + kq;
        int brow = bn + m;
        bSz[i] = (brow < N) ? 16u : 0u;
        if (brow >= N) brow = N - 1;
        bP[i]  = W + (size_t)brow * ldb + kstart + kq;
    }

    // prologue: stages 0 and 1
#pragma unroll
    for (int st = 0; st < 2; st++) {
        if (st < ntile) {
            const uint32_t so = (uint32_t)st * 16384u;
#pragma unroll
            for (int i = 0; i < 4; i++) {
                CP16(aSm[i] + so, aP[i], 16u);
                CP16(bSm[i] + so, bP[i], bSz[i]);
                aP[i] += 32; bP[i] += 32;
            }
            asm volatile("cp.async.commit_group;");
        }
    }

    const int swz = grp << 2;

    for (int t = 0; t < ntile; t++) {
        if (t + 2 < ntile) {
            const int st = (t + 2) % 3;
            const uint32_t so = (uint32_t)st * 16384u;
#pragma unroll
            for (int i = 0; i < 4; i++) {
                CP16(aSm[i] + so, aP[i], 16u);
                CP16(bSm[i] + so, bP[i], bSz[i]);
                aP[i] += 32; bP[i] += 32;
            }
            asm volatile("cp.async.commit_group;");
            asm volatile("cp.async.wait_group 2;");
        } else if (t + 1 < ntile) {
            asm volatile("cp.async.wait_group 1;");
        } else {
            asm volatile("cp.async.wait_group 0;");
        }
        __syncthreads();

        const int buf = (t % 3) * 4096;
#pragma unroll
        for (int ks = 0; ks < 4; ks++) {
            const int kb = ks * 8;
            const int c0 = (kb + tig) ^ swz;
            const int c1 = (kb + tig + 4) ^ swz;
            uint32_t af[4][4], bf[4][2];
#pragma unroll
            for (int mt = 0; mt < 4; mt++) {
                int r0 = (wm * 64 + mt * 16 + grp) * 32;
                af[mt][0] = __float_as_uint(As[buf + r0 + c0]);
                af[mt][1] = __float_as_uint(As[buf + r0 + 256 + c0]);
                af[mt][2] = __float_as_uint(As[buf + r0 + c1]);
                af[mt][3] = __float_as_uint(As[buf + r0 + 256 + c1]);
            }
#pragma unroll
            for (int nt = 0; nt < 4; nt++) {
                int r0 = (wn * 32 + nt * 8 + grp) * 32;
                bf[nt][0] = __float_as_uint(Bs[buf + r0 + c0]);
                bf[nt][1] = __float_as_uint(Bs[buf + r0 + c1]);
            }
#pragma unroll
            for (int mt = 0; mt < 4; mt++)
#pragma unroll
                for (int nt = 0; nt < 4; nt++)
                    mma_tf32(acc[mt][nt], af[mt], bf[nt]);
        }
        __syncthreads();
    }

    float* Cp = C + (size_t)blockIdx.z * partStride;
    const bool doBias = (bias != nullptr) && (gridDim.z == 1);
#pragma unroll
    for (int mt = 0; mt < 4; mt++) {
#pragma unroll
        for (int nt = 0; nt < 4; nt++) {
            int row = bm + wm * 64 + mt * 16 + grp;
            int col = bn + wn * 32 + nt * 8 + tig * 2;
            if (col >= N) continue;
            float b0 = doBias ? __ldg(bias + col) : 0.0f;
            float b1 = doBias ? __ldg(bias + col + 1) : 0.0f;
            float v0 = acc[mt][nt][0] + b0, v1 = acc[mt][nt][1] + b1;
            float v2 = acc[mt][nt][2] + b0, v3 = acc[mt][nt][3] + b1;
            if (epi == 1) {
                v0 = softplusf(v0); v1 = softplusf(v1);
                v2 = softplusf(v2); v3 = softplusf(v3);
            }
            if (col < nRound) {
                v0 = roundtf(v0); v1 = roundtf(v1);
                v2 = roundtf(v2); v3 = roundtf(v3);
            }
            float2 lo = make_float2(v0, v1), hi = make_float2(v2, v3);
            *(float2*)&Cp[(size_t)row * ldc + col] = lo;
            *(float2*)&Cp[(size_t)(row + 8) * ldc + col] = hi;
        }
    }
}

// ---------------- split-K reduction (rounds output) ------------------------------
__global__ void reduce_splitk(const float* __restrict__ part,
                              float* __restrict__ out, int n)
{
    int i = blockIdx.x * blockDim.x + threadIdx.x;
    if (i < n) {
        float s = 0.0f;
#pragma unroll
        for (int z = 0; z < KSPLIT; z++) s += part[(size_t)z * n + i];
        out[i] = roundtf(s);
    }
}

// ---------------- ada = silu(c) @ Wada^T + bada  (warp per output) ---------------
__global__ __launch_bounds__(256) void ada_kernel(
    const float* __restrict__ c, const float* __restrict__ Wada,
    const float* __restrict__ bada, float* __restrict__ ada)
{
    int w    = (blockIdx.x * blockDim.x + threadIdx.x) >> 5;   // 0..6143
    int lane = threadIdx.x & 31;
    int b = (w >= THREED) ? 1 : 0;
    int o = w - b * THREED;

    const float4* cp = (const float4*)(c + b * 2 * Dd);
    const float4* wp = (const float4*)(Wada + (size_t)o * 2 * Dd);
    float s = 0.0f;
#pragma unroll
    for (int it = 0; it < 16; it++) {
        float4 cv = __ldg(&cp[lane + it * 32]);
        float4 wv = __ldg(&wp[lane + it * 32]);
        s += siluf(cv.x) * wv.x + siluf(cv.y) * wv.y
           + siluf(cv.z) * wv.z + siluf(cv.w) * wv.w;
    }
#pragma unroll
    for (int off = 16; off; off >>= 1) s += __shfl_xor_sync(0xffffffffu, s, off);
    if (lane == 0) ada[b * THREED + o] = s + __ldg(bada + o);
}

// ---------------- fused LN1 + modulate(+store skip) + LN2 (xn rounded) -----------
__global__ __launch_bounds__(256) void ln_mod_kernel(
    const float* __restrict__ x,
    const float* __restrict__ g1, const float* __restrict__ b1,
    const float* __restrict__ g2, const float* __restrict__ b2,
    const float* __restrict__ ada,
    float* __restrict__ skip, float* __restrict__ xn)
{
    __shared__ float sh[8];
    const int row = blockIdx.x;
    const int b = row >> 10;
    const float* xr = x + (size_t)row * Dd;

    float v[4];
#pragma unroll
    for (int j = 0; j < 4; j++) v[j] = xr[threadIdx.x + j * 256];

    float s1 = 0.0f, s2 = 0.0f;
#pragma unroll
    for (int j = 0; j < 4; j++) { s1 += v[j]; s2 += v[j] * v[j]; }
    s1 = blockReduceSum(s1, sh);
    s2 = blockReduceSum(s2, sh);
    float m  = s1 * (1.0f / Dd);
    float rs = rsqrtf(s2 * (1.0f / Dd) - m * m + 1e-5f);

    float t[4];
    s1 = 0.0f; s2 = 0.0f;
#pragma unroll
    for (int j = 0; j < 4; j++) {
        int d = threadIdx.x + j * 256;
        float tt = (v[j] - m) * rs * g1[d] + b1[d];
        tt = tt * (1.0f + ada[b * THREED + Dd + d]) + ada[b * THREED + d];
        t[j] = tt;
        skip[(size_t)row * Dd + d] = tt;
        s1 += tt; s2 += tt * tt;
    }
    s1 = blockReduceSum(s1, sh);
    s2 = blockReduceSum(s2, sh);
    float m2  = s1 * (1.0f / Dd);
    float rs2 = rsqrtf(s2 * (1.0f / Dd) - m2 * m2 + 1e-5f);

#pragma unroll
    for (int j = 0; j < 4; j++) {
        int d = threadIdx.x + j * 256;
        xn[(size_t)row * Dd + d] = roundtf((t[j] - m2) * rs2 * g2[d] + b2[d]);
    }
}

// ---------------- SMEM-staged selective scan -------------------------------------
// Block = 16 consecutive e for one (branch, b). 256 threads = 16 half-warp units.
// z comes from the merged z12 buffer (row stride ldz=4096); branch 1 reversed.
__global__ __launch_bounds__(256) void scan_smem_kernel(
    const float* __restrict__ de1, const float* __restrict__ de2,
    const float* __restrict__ z12, int ldz,
    const float* __restrict__ dbc1, const float* __restrict__ dbc2,
    const float* __restrict__ Alog1, const float* __restrict__ Alog2,
    const float* __restrict__ Dp1, const float* __restrict__ Dp2,
    float* __restrict__ gg1, float* __restrict__ gg2)
{
    __shared__ float deS[2][SCH][16];
    __shared__ float zS [2][SCH][16];
    __shared__ float bcS[2][SCH][32];
    __shared__ float ggS[SCH][16];

    const int tid = threadIdx.x;
    const int u   = tid >> 4;
    const int n   = tid & 15;

    const int bx = blockIdx.x;         // 0..511
    const int et = bx & 127;
    const int b  = (bx >> 7) & 1;
    const int br = bx >> 8;
    const int e0 = et * 16;

    const float* de   = br ? de2  : de1;
    const float* z    = z12 + (br ? Ee : 0);
    const float* dbc  = br ? dbc2 : dbc1;
    const float* Alog = br ? Alog2 : Alog1;
    const float* Dp   = br ? Dp2  : Dp1;
    float*       gg   = br ? gg2  : gg1;

    const int e = e0 + u;
    const float A_n  = -__expf(Alog[e * Nn + n]);
    const float Dp_e = Dp[e];

    const size_t rowBase = (size_t)b * Ss;

    uint32_t deSm = (uint32_t)__cvta_generic_to_shared(&deS[0][0][0]);
    uint32_t zSm  = (uint32_t)__cvta_generic_to_shared(&zS[0][0][0]);
    uint32_t bcSm = (uint32_t)__cvta_generic_to_shared(&bcS[0][0][0]);

    const int lr  = tid >> 2;
    const int lp  = (tid & 3) * 4;
    const int br0 = (tid * 2) >> 3;
    const int bp0 = ((tid * 2) & 7) * 4;
    const int br1 = (tid * 2 + 1) >> 3;
    const int bp1 = ((tid * 2 + 1) & 7) * 4;

    auto loadChunk = [&](int c, int buf) {
        int s = br ? (Ss - 1 - (c * SCH + lr)) : (c * SCH + lr);
        const float* gd = de + (rowBase + s) * Ee + e0 + lp;
        const float* gz = z  + (rowBase + s) * (size_t)ldz + e0 + lp;
        CP16F(deSm + (uint32_t)((buf * SCH + lr) * 16 + lp) * 4u, gd);
        CP16F(zSm  + (uint32_t)((buf * SCH + lr) * 16 + lp) * 4u, gz);
        int s0 = br ? (Ss - 1 - (c * SCH + br0)) : (c * SCH + br0);
        int s1b = br ? (Ss - 1 - (c * SCH + br1)) : (c * SCH + br1);
        const float* g0 = dbc + (rowBase + s0) * DBCW + Rr + bp0;
        const float* g1 = dbc + (rowBase + s1b) * DBCW + Rr + bp1;
        CP16F(bcSm + (uint32_t)((buf * SCH + br0) * 32 + bp0) * 4u, g0);
        CP16F(bcSm + (uint32_t)((buf * SCH + br1) * 32 + bp1) * 4u, g1);
    };

    loadChunk(0, 0);
    asm volatile("cp.async.commit_group;");

    float h = 0.0f;

    for (int c = 0; c < NCH; c++) {
        if (c + 1 < NCH) {
            loadChunk(c + 1, (c + 1) & 1);
            asm volatile("cp.async.commit_group;");
            asm volatile("cp.async.wait_group 1;");
        } else {
            asm volatile("cp.async.wait_group 0;");
        }
        __syncthreads();

        const int buf = c & 1;
#pragma unroll 8
        for (int cs = 0; cs < SCH; cs++) {
            float dlt = deS[buf][cs][u];
            float uu  = zS[buf][cs][u];
            float Bv  = bcS[buf][cs][n];
            float Cv  = bcS[buf][cs][16 + n];

            h = __expf(dlt * A_n) * h + dlt * Bv * uu;
            float y = h * Cv;
            y += __shfl_xor_sync(0xffffffffu, y, 8);
            y += __shfl_xor_sync(0xffffffffu, y, 4);
            y += __shfl_xor_sync(0xffffffffu, y, 2);
            y += __shfl_xor_sync(0xffffffffu, y, 1);
            if (n == 0) ggS[cs][u] = y + uu * Dp_e;
        }
        __syncthreads();

        {
            int r = tid >> 2, p = (tid & 3) * 4;
            int s = br ? (Ss - 1 - (c * SCH + r)) : (c * SCH + r);
            *(float4*)&gg[(rowBase + s) * Ee + e0 + p] = *(float4*)&ggS[r][p];
        }
    }
}

// ---------------- acmb = silu(mx) * (gg1 + gg2), rounded --------------------------
__global__ void combine_kernel(const float4* __restrict__ mzx,
                               const float4* __restrict__ gg1,
                               const float4* __restrict__ gg2,
                               float4* __restrict__ a, int n4)
{
    int i = blockIdx.x * blockDim.x + threadIdx.x;
    if (i < n4) {
        int row  = i >> 9;              // / (Ee/4)
        int col4 = i & 511;
        float4 m = mzx[row * 1024 + 512 + col4];   // mx half (ld=4096 floats)
        float4 p = gg1[i], q = gg2[i], r;
        r.x = roundtf(siluf(m.x) * (p.x + q.x));
        r.y = roundtf(siluf(m.y) * (p.y + q.y));
        r.z = roundtf(siluf(m.z) * (p.z + q.z));
        r.w = roundtf(siluf(m.w) * (p.w + q.w));
        a[i] = r;
    }
}

// ---------------- out = x + gate * (tmp + skip) -----------------------------------
__global__ void final_kernel(const float4* __restrict__ x,
                             const float* __restrict__ ada,
                             const float4* __restrict__ tmp,
                             const float4* __restrict__ skip,
                             float4* __restrict__ out, int n4)
{
    int i = blockIdx.x * blockDim.x + threadIdx.x;
    if (i < n4) {
        int d4  = i & (Dd / 4 - 1);
        int b   = i >> 18;
        const float4 g = *(const float4*)&ada[b * THREED + 2 * Dd + d4 * 4];
        float4 xv = x[i], tv = tmp[i], sv = skip[i], o;
        o.x = xv.x + g.x * (tv.x + sv.x);
        o.y = xv.y + g.y * (tv.y + sv.y);
        o.z = xv.z + g.z * (tv.z + sv.z);
        o.w = xv.w + g.w * (tv.w + sv.w);
        out[i] = o;
    }
}

// ---------------- host launcher ----------------------------------------------------
extern "C" void kernel_launch(void* const* d_in, const int* in_sizes, int n_in,
                              void* d_out, int out_size)
{
    const float* x     = (const float*)d_in[0];
    const float* c     = (const float*)d_in[1];
    const float* n1g   = (const float*)d_in[3];
    const float* n1b   = (const float*)d_in[4];
    const float* n2g   = (const float*)d_in[5];
    const float* n2b   = (const float*)d_in[6];
    const float* Wx    = (const float*)d_in[7];
    const float* bx    = (const float*)d_in[8];
    const float* Wz    = (const float*)d_in[9];
    const float* bz    = (const float*)d_in[10];
    const float* Wf    = (const float*)d_in[11];
    const float* bf    = (const float*)d_in[12];
    const float* Wada  = (const float*)d_in[13];
    const float* bada  = (const float*)d_in[14];
    const float* Wc1   = (const float*)d_in[15];
    const float* bc1   = (const float*)d_in[16];
    const float* Wc2   = (const float*)d_in[17];
    const float* bc2   = (const float*)d_in[18];
    const float* Wdbc1 = (const float*)d_in[19];
    const float* Wdt1  = (const float*)d_in[20];
    const float* bdt1  = (const float*)d_in[21];
    const float* Alog1 = (const float*)d_in[22];
    const float* Dp1   = (const float*)d_in[23];
    const float* Wdbc2 = (const float*)d_in[24];
    const float* Wdt2  = (const float*)d_in[25];
    const float* bdt2  = (const float*)d_in[26];
    const float* Alog2 = (const float*)d_in[27];
    const float* Dp2   = (const float*)d_in[28];
    float* out = (float*)d_out;

    float *ada, *skip, *xn, *mzx, *z12, *dbc1, *dbc2;
    float *de1, *de2, *gg1, *gg2, *acmb, *tmp, *part;
    float *wzx, *wc12, *wdbc1, *wdbc2, *wdt1, *wdt2, *wf, *bzx, *bc12;
    cudaGetSymbolAddress((void**)&ada,  g_ada);
    cudaGetSymbolAddress((void**)&skip, g_skip);
    cudaGetSymbolAddress((void**)&xn,   g_xn);
    cudaGetSymbolAddress((void**)&mzx,  g_mzx);
    cudaGetSymbolAddress((void**)&z12,  g_z12);
    cudaGetSymbolAddress((void**)&dbc1, g_dbc1);
    cudaGetSymbolAddress((void**)&dbc2, g_dbc2);
    cudaGetSymbolAddress((void**)&de1,  g_del1);
    cudaGetSymbolAddress((void**)&de2,  g_del2);
    cudaGetSymbolAddress((void**)&gg1,  g_gg1);
    cudaGetSymbolAddress((void**)&gg2,  g_gg2);
    cudaGetSymbolAddress((void**)&acmb, g_acmb);
    cudaGetSymbolAddress((void**)&tmp,  g_tmp);
    cudaGetSymbolAddress((void**)&part, g_part);
    cudaGetSymbolAddress((void**)&wzx,   g_wzx);
    cudaGetSymbolAddress((void**)&wc12,  g_wc12);
    cudaGetSymbolAddress((void**)&wdbc1, g_wdbc1);
    cudaGetSymbolAddress((void**)&wdbc2, g_wdbc2);
    cudaGetSymbolAddress((void**)&wdt1,  g_wdt1);
    cudaGetSymbolAddress((void**)&wdt2,  g_wdt2);
    cudaGetSymbolAddress((void**)&wf,    g_wf);
    cudaGetSymbolAddress((void**)&bzx,   g_bzx);
    cudaGetSymbolAddress((void**)&bc12,  g_bc12);

    const int SMEM = 98304;   // 3-stage pipeline: 2 x 3 x 16KB
    cudaFuncSetAttribute(gemm_tf32, cudaFuncAttributeMaxDynamicSharedMemorySize, SMEM);

    auto roundW = [&](const float* src, float* dst, int nElem) {
        int n4 = nElem / 4;
        round_tf32_kernel<<<(n4 + 255) / 256, 256>>>(
            (const float4*)src, (float4*)dst, n4);
    };

    // 1/2. round + stack [Wz; Wx]
    roundW(Wz, wzx, Ee * Dd);
    roundW(Wx, wzx + (size_t)Ee * Dd, Ee * Dd);
    // 3. bzx = [bz; bx]
    concat2_kernel<<<(2 * Ee + 255) / 256, 256>>>(bz, bx, bzx, Ee);
    // 4. ada = silu(c) @ Wada^T + bada  (warp per output)
    ada_kernel<<<768, 256>>>(c, Wada, bada, ada);
    // 5. LN1 + modulate (-> skip) + LN2 (-> xn, rounded)
    ln_mod_kernel<<<BSr, 256>>>(x, n1g, n1b, n2g, n2b, ada, skip, xn);
    // 6. merged mz|mx  [2048, 4096] K=1024   <-- ncu-profiled launch (#6)
    gemm_tf32<<<dim3(2 * Ee / 128, BSr / 128, 1), 256, SMEM>>>(
        xn, Dd, wzx, Dd, bzx, mzx, 2 * Ee, BSr, 2 * Ee, Dd, 0, Ee, 0);

    // 7/8/9. round + stack [Wc1; Wc2], bc12
    roundW(Wc1, wc12, Ee * Ee);
    roundW(Wc2, wc12 + (size_t)Ee * Ee, Ee * Ee);
    concat2_kernel<<<(2 * Ee + 255) / 256, 256>>>(bc1, bc2, bc12, Ee);
    // 10. merged z1|z2  [2048, 4096] K=2048 (A = mz half of mzx, lda=4096)
    gemm_tf32<<<dim3(2 * Ee / 128, BSr / 128, 1), 256, SMEM>>>(
        mzx, 2 * Ee, wc12, Ee, bc12, z12, 2 * Ee, BSr, 2 * Ee, Ee, 0, 2 * Ee, 0);

    // 11-16. dbc = z @ Wdbc^T  [2048, 96] K=2048  (split-K=8, rounded in reduce)
    roundW(Wdbc1, wdbc1, DBCW * Ee);
    gemm_tf32<<<dim3(1, BSr / 128, KSPLIT), 256, SMEM>>>(
        z12, 2 * Ee, wdbc1, Ee, nullptr, part, DBCW, BSr, DBCW, Ee, 0, 0, BSr * DBCW);
    reduce_splitk<<<(BSr * DBCW + 255) / 256, 256>>>(part, dbc1, BSr * DBCW);
    roundW(Wdbc2, wdbc2, DBCW * Ee);
    gemm_tf32<<<dim3(1, BSr / 128, KSPLIT), 256, SMEM>>>(
        z12 + Ee, 2 * Ee, wdbc2, Ee, nullptr, part, DBCW, BSr, DBCW, Ee, 0, 0, BSr * DBCW);
    reduce_splitk<<<(BSr * DBCW + 255) / 256, 256>>>(part, dbc2, BSr * DBCW);

    // 17-20. delta = softplus(dlt @ Wdt^T + bdt)  [2048, 2048] K=64
    roundW(Wdt1, wdt1, Ee * Rr);
    gemm_tf32<<<dim3(Ee / 128, BSr / 128, 1), 256, SMEM>>>(
        dbc1, DBCW, wdt1, Rr, bdt1, de1, Ee, BSr, Ee, Rr, 1, 0, 0);
    roundW(Wdt2, wdt2, Ee * Rr);
    gemm_tf32<<<dim3(Ee / 128, BSr / 128, 1), 256, SMEM>>>(
        dbc2, DBCW, wdt2, Rr, bdt2, de2, Ee, BSr, Ee, Rr, 1, 0, 0);

    // 21. both selective scans, SMEM-staged
    scan_smem_kernel<<<512, 256>>>(de1, de2, z12, 2 * Ee, dbc1, dbc2,
                                   Alog1, Alog2, Dp1, Dp2, gg1, gg2);

    // 22. acmb = silu(mx) * (gg1 + gg2), rounded
    combine_kernel<<<(BSr * Ee / 4 + 255) / 256, 256>>>(
        (const float4*)mzx, (const float4*)gg1, (const float4*)gg2,
        (float4*)acmb, BSr * Ee / 4);

    // 23/24. tmp = acmb @ Wf^T + bf  [2048, 1024] K=2048
    roundW(Wf, wf, Dd * Ee);
    gemm_tf32<<<dim3(Dd / 128, BSr / 128, 1), 256, SMEM>>>(
        acmb, Ee, wf, Ee, bf, tmp, Dd, BSr, Dd, Ee, 0, 0, 0);

    // 25. out = x + gate * (tmp + skip)
    final_kernel<<<(BSr * Dd / 4 + 255) / 256, 256>>>(
        (const float4*)x, ada, (const float4*)tmp, (const float4*)skip,
        (float4*)out, BSr * Dd / 4);
}

// round 9
// speedup vs baseline: 4.6143x; 1.0447x over previous
#include <cuda_runtime.h>
#include <cuda_bf16.h>
#include <math.h>
#include <stdint.h>

// Problem constants
#define Bb   2
#define Ss   1024
#define Dd   1024
#define Ee   2048
#define Nn   16
#define Rr   64
#define BSr  (Bb * Ss)          // 2048 rows
#define DBCW (Rr + 2 * Nn)      // 96
#define THREED (3 * Dd)         // 3072
#define KSPLIT 8
#define SCH  64                 // scan chunk (steps per SMEM stage)
#define NCH  (Ss / SCH)         // 16 chunks

// ---------------- scratch (device globals; no allocation in kernel_launch) ----
__device__ float g_ada  [Bb * THREED];
__device__ float g_skip [BSr * Dd];
__device__ float g_xn   [BSr * Dd];
__device__ float g_mzx  [BSr * 2 * Ee];      // mz | mx  (ld = 4096)
__device__ float g_z12  [BSr * 2 * Ee];      // z1 | z2  (ld = 4096)
__device__ float g_dbc1 [BSr * DBCW];
__device__ float g_dbc2 [BSr * DBCW];
__device__ float g_del1 [BSr * Ee];
__device__ float g_del2 [BSr * Ee];
__device__ float g_gg1  [BSr * Ee];
__device__ float g_gg2  [BSr * Ee];
__device__ float g_acmb [BSr * Ee];
__device__ float g_tmp  [BSr * Dd];
__device__ float g_part [2 * KSPLIT * BSr * DBCW];
// pre-rounded (tf32) weights / concat biases
__device__ float g_wzx  [2 * Ee * Dd];       // [Wz ; Wx] rounded
__device__ float g_wc12 [2 * Ee * Ee];       // [Wc1 ; Wc2] rounded
__device__ float g_wdbc1[DBCW * Ee];
__device__ float g_wdbc2[DBCW * Ee];
__device__ float g_wdt1 [Ee * Rr];
__device__ float g_wdt2 [Ee * Rr];
__device__ float g_wf   [Dd * Ee];
__device__ float g_bzx  [2 * Ee];            // [bz ; bx]
__device__ float g_bc12 [2 * Ee];            // [bc1 ; bc2]

// ---------------- helpers -----------------------------------------------------
__device__ __forceinline__ float siluf(float v) { return v / (1.0f + __expf(-v)); }
__device__ __forceinline__ float softplusf(float v) {
    return (v > 20.0f) ? v : log1pf(__expf(v));
}
__device__ __forceinline__ uint32_t f2tf32(float f) {
    uint32_t u;
    asm("cvt.rna.tf32.f32 %0, %1;" : "=r"(u) : "f"(f));
    return u;
}
__device__ __forceinline__ float roundtf(float f) {
    return __uint_as_float(f2tf32(f));
}
__device__ __forceinline__ void mma_tf32(float* c, const uint32_t* a, const uint32_t* b) {
    asm volatile(
        "mma.sync.aligned.m16n8k8.row.col.f32.tf32.tf32.f32 "
        "{%0,%1,%2,%3},{%4,%5,%6,%7},{%8,%9},{%0,%1,%2,%3};"
        : "+f"(c[0]), "+f"(c[1]), "+f"(c[2]), "+f"(c[3])
        : "r"(a[0]), "r"(a[1]), "r"(a[2]), "r"(a[3]), "r"(b[0]), "r"(b[1]));
}
#define CP16(dst, src, sz) \
    asm volatile("cp.async.cg.shared.global [%0], [%1], 16, %2;" \
                 :: "r"(dst), "l"(src), "r"(sz))
#define CP16F(dst, src) \
    asm volatile("cp.async.cg.shared.global [%0], [%1], 16;" \
                 :: "r"(dst), "l"(src))

__device__ __forceinline__ float blockReduceSum(float v, float* sh) {
    int lane = threadIdx.x & 31, wid = threadIdx.x >> 5;
#pragma unroll
    for (int o = 16; o; o >>= 1) v += __shfl_xor_sync(0xffffffffu, v, o);
    __syncthreads();
    if (lane == 0) sh[wid] = v;
    __syncthreads();
    if (wid == 0) {
        v = (lane < 8) ? sh[lane] : 0.0f;
#pragma unroll
        for (int o = 4; o; o >>= 1) v += __shfl_xor_sync(0xffffffffu, v, o);
        if (lane == 0) sh[0] = v;
    }
    __syncthreads();
    return sh[0];
}

// ---------------- fused weight round + bias concat (13 segments) ----------------
#define NSEG 13
struct RoundJobs {
    const float4* src[NSEG];
    float4*       dst[NSEG];
    int           off[NSEG + 1];   // start offset (in float4) of each segment
    int           rnd[NSEG];       // 1 = round to tf32
};

__global__ void round_all_kernel(RoundJobs jb, int total4) {
    int i = blockIdx.x * blockDim.x + threadIdx.x;
    if (i >= total4) return;
    int s = 0;
#pragma unroll
    for (int k = 1; k < NSEG; k++) if (i >= jb.off[k]) s = k;
    int j = i - jb.off[s];
    float4 v = jb.src[s][j];
    if (jb.rnd[s]) {
        v.x = roundtf(v.x); v.y = roundtf(v.y);
        v.z = roundtf(v.z); v.w = roundtf(v.w);
    }
    jb.dst[s][j] = v;
}

// ---------------- tf32 tensor-core GEMM (3-stage cp.async, batched) -------------
// C[M,N] = A[M,K] * W[N,K]^T (+bias, +epi). Tile 128x128x32, 256 threads,
// 8 warps (2x4), warp tile 64x32, mma m16n8k8 tf32. 3-stage cp.async pipeline,
// XOR-swizzled SMEM. Inputs must be tf32-pre-rounded.
// epi: 0 none, 1 softplus. nRound: columns [0,nRound) rna-rounded on store.
// Batching: blockIdx.z in [0, splitK * nBranch). branch = z / splitK selects
// (A2,W2,bias2,C2); kslice = z % splitK. Output at C + z*partStride
// (bias applied only when splitK == 1).
__global__ __launch_bounds__(256, 2) void gemm_tf32(
    const float* __restrict__ A_, int lda,
    const float* __restrict__ W_, int ldb,
    const float* __restrict__ bias_,
    float* __restrict__ C_, int ldc,
    int M, int N, int K, int epi, int nRound, int splitK, int partStride,
    const float* A2, const float* W2, const float* bias2, float* C2)
{
    extern __shared__ float smf[];
    float* As = smf;             // [3][128*32]
    float* Bs = smf + 12288;     // [3][128*32]

    const float* A = A_;
    const float* W = W_;
    const float* bias = bias_;
    float* C = C_;

    const int bz = blockIdx.z;
    const int br = bz / splitK;
    const int kz = bz % splitK;
    if (br == 1) { A = A2; W = W2; bias = bias2; if (C2) C = C2; }

    const int tid  = threadIdx.x;
    const int wid  = tid >> 5, lane = tid & 31;
    const int wm   = wid >> 2, wn = wid & 3;
    const int grp  = lane >> 2, tig = lane & 3;
    const int bm   = blockIdx.y * 128, bn = blockIdx.x * 128;
    const int klen   = K / splitK;
    const int kstart = kz * klen;
    const int ntile  = klen >> 5;

    float acc[4][4][4];
#pragma unroll
    for (int i = 0; i < 4; i++)
#pragma unroll
        for (int j = 0; j < 4; j++)
#pragma unroll
            for (int r = 0; r < 4; r++) acc[i][j][r] = 0.0f;

    uint32_t aSm[4], bSm[4], bSz[4];
    const float* aP[4];
    const float* bP[4];
    const uint32_t sA = (uint32_t)__cvta_generic_to_shared(As);
    const uint32_t sB = (uint32_t)__cvta_generic_to_shared(Bs);
#pragma unroll
    for (int i = 0; i < 4; i++) {
        int f = tid + i * 256;
        int m = f >> 3, kq = (f & 7) * 4;
        int col = kq ^ ((m & 7) << 2);
        aSm[i] = sA + (uint32_t)(m * 32 + col) * 4u;
        bSm[i] = sB + (uint32_t)(m * 32 + col) * 4u;
        aP[i]  = A + (size_t)(bm + m) * lda + kstart + kq;
        int brow = bn + m;
        bSz[i] = (brow < N) ? 16u : 0u;
        if (brow >= N) brow = N - 1;
        bP[i]  = W + (size_t)brow * ldb + kstart + kq;
    }

    // prologue: stages 0 and 1
#pragma unroll
    for (int st = 0; st < 2; st++) {
        if (st < ntile) {
            const uint32_t so = (uint32_t)st * 16384u;
#pragma unroll
            for (int i = 0; i < 4; i++) {
                CP16(aSm[i] + so, aP[i], 16u);
                CP16(bSm[i] + so, bP[i], bSz[i]);
                aP[i] += 32; bP[i] += 32;
            }
            asm volatile("cp.async.commit_group;");
        }
    }

    const int swz = grp << 2;

    for (int t = 0; t < ntile; t++) {
        if (t + 2 < ntile) {
            const int st = (t + 2) % 3;
            const uint32_t so = (uint32_t)st * 16384u;
#pragma unroll
            for (int i = 0; i < 4; i++) {
                CP16(aSm[i] + so, aP[i], 16u);
                CP16(bSm[i] + so, bP[i], bSz[i]);
                aP[i] += 32; bP[i] += 32;
            }
            asm volatile("cp.async.commit_group;");
            asm volatile("cp.async.wait_group 2;");
        } else if (t + 1 < ntile) {
            asm volatile("cp.async.wait_group 1;");
        } else {
            asm volatile("cp.async.wait_group 0;");
        }
        __syncthreads();

        const int buf = (t % 3) * 4096;
#pragma unroll
        for (int ks = 0; ks < 4; ks++) {
            const int kb = ks * 8;
            const int c0 = (kb + tig) ^ swz;
            const int c1 = (kb + tig + 4) ^ swz;
            uint32_t af[4][4], bf[4][2];
#pragma unroll
            for (int mt = 0; mt < 4; mt++) {
                int r0 = (wm * 64 + mt * 16 + grp) * 32;
                af[mt][0] = __float_as_uint(As[buf + r0 + c0]);
                af[mt][1] = __float_as_uint(As[buf + r0 + 256 + c0]);
                af[mt][2] = __float_as_uint(As[buf + r0 + c1]);
                af[mt][3] = __float_as_uint(As[buf + r0 + 256 + c1]);
            }
#pragma unroll
            for (int nt = 0; nt < 4; nt++) {
                int r0 = (wn * 32 + nt * 8 + grp) * 32;
                bf[nt][0] = __float_as_uint(Bs[buf + r0 + c0]);
                bf[nt][1] = __float_as_uint(Bs[buf + r0 + c1]);
            }
#pragma unroll
            for (int mt = 0; mt < 4; mt++)
#pragma unroll
                for (int nt = 0; nt < 4; nt++)
                    mma_tf32(acc[mt][nt], af[mt], bf[nt]);
        }
        __syncthreads();
    }

    float* Cp = C + (size_t)bz * partStride;
    const bool doBias = (bias != nullptr) && (splitK == 1);
#pragma unroll
    for (int mt = 0; mt < 4; mt++) {
#pragma unroll
        for (int nt = 0; nt < 4; nt++) {
            int row = bm + wm * 64 + mt * 16 + grp;
            int col = bn + wn * 32 + nt * 8 + tig * 2;
            if (col >= N) continue;
            float b0 = doBias ? __ldg(bias + col) : 0.0f;
            float b1 = doBias ? __ldg(bias + col + 1) : 0.0f;
            float v0 = acc[mt][nt][0] + b0, v1 = acc[mt][nt][1] + b1;
            float v2 = acc[mt][nt][2] + b0, v3 = acc[mt][nt][3] + b1;
            if (epi == 1) {
                v0 = softplusf(v0); v1 = softplusf(v1);
                v2 = softplusf(v2); v3 = softplusf(v3);
            }
            if (col < nRound) {
                v0 = roundtf(v0); v1 = roundtf(v1);
                v2 = roundtf(v2); v3 = roundtf(v3);
            }
            float2 lo = make_float2(v0, v1), hi = make_float2(v2, v3);
            *(float2*)&Cp[(size_t)row * ldc + col] = lo;
            *(float2*)&Cp[(size_t)(row + 8) * ldc + col] = hi;
        }
    }
}

// ---------------- split-K reduction for both branches (rounds output) ------------
__global__ void reduce_splitk2(const float* __restrict__ part,
                               float* __restrict__ out1,
                               float* __restrict__ out2, int n)
{
    int i = blockIdx.x * blockDim.x + threadIdx.x;
    if (i < 2 * n) {
        int br = (i >= n);
        int j  = i - br * n;
        const float* p = part + (size_t)(br * KSPLIT) * n + j;
        float s = 0.0f;
#pragma unroll
        for (int z = 0; z < KSPLIT; z++) s += p[(size_t)z * n];
        float v = roundtf(s);
        if (br) out2[j] = v; else out1[j] = v;
    }
}

// ---------------- ada: one warp computes both batch outputs ----------------------
__global__ __launch_bounds__(256) void ada_kernel(
    const float* __restrict__ c, const float* __restrict__ Wada,
    const float* __restrict__ bada, float* __restrict__ ada)
{
    int w    = (blockIdx.x * blockDim.x + threadIdx.x) >> 5;   // 0..3071
    int lane = threadIdx.x & 31;

    const float4* wp  = (const float4*)(Wada + (size_t)w * 2 * Dd);
    const float4* c0p = (const float4*)c;
    const float4* c1p = (const float4*)(c + 2 * Dd);
    float s0 = 0.0f, s1 = 0.0f;
#pragma unroll
    for (int it = 0; it < 16; it++) {
        float4 wv = __ldg(&wp[lane + it * 32]);
        float4 a0 = __ldg(&c0p[lane + it * 32]);
        float4 a1 = __ldg(&c1p[lane + it * 32]);
        s0 += siluf(a0.x) * wv.x + siluf(a0.y) * wv.y
            + siluf(a0.z) * wv.z + siluf(a0.w) * wv.w;
        s1 += siluf(a1.x) * wv.x + siluf(a1.y) * wv.y
            + siluf(a1.z) * wv.z + siluf(a1.w) * wv.w;
    }
#pragma unroll
    for (int off = 16; off; off >>= 1) {
        s0 += __shfl_xor_sync(0xffffffffu, s0, off);
        s1 += __shfl_xor_sync(0xffffffffu, s1, off);
    }
    if (lane == 0) {
        float bv = __ldg(bada + w);
        ada[w] = s0 + bv;
        ada[THREED + w] = s1 + bv;
    }
}

// ---------------- fused LN1 + modulate(+store skip) + LN2 (xn rounded) -----------
__global__ __launch_bounds__(256) void ln_mod_kernel(
    const float* __restrict__ x,
    const float* __restrict__ g1, const float* __restrict__ b1,
    const float* __restrict__ g2, const float* __restrict__ b2,
    const float* __restrict__ ada,
    float* __restrict__ skip, float* __restrict__ xn)
{
    __shared__ float sh[8];
    const int row = blockIdx.x;
    const int b = row >> 10;
    const float* xr = x + (size_t)row * Dd;

    float v[4];
#pragma unroll
    for (int j = 0; j < 4; j++) v[j] = xr[threadIdx.x + j * 256];

    float s1 = 0.0f, s2 = 0.0f;
#pragma unroll
    for (int j = 0; j < 4; j++) { s1 += v[j]; s2 += v[j] * v[j]; }
    s1 = blockReduceSum(s1, sh);
    s2 = blockReduceSum(s2, sh);
    float m  = s1 * (1.0f / Dd);
    float rs = rsqrtf(s2 * (1.0f / Dd) - m * m + 1e-5f);

    float t[4];
    s1 = 0.0f; s2 = 0.0f;
#pragma unroll
    for (int j = 0; j < 4; j++) {
        int d = threadIdx.x + j * 256;
        float tt = (v[j] - m) * rs * g1[d] + b1[d];
        tt = tt * (1.0f + ada[b * THREED + Dd + d]) + ada[b * THREED + d];
        t[j] = tt;
        skip[(size_t)row * Dd + d] = tt;
        s1 += tt; s2 += tt * tt;
    }
    s1 = blockReduceSum(s1, sh);
    s2 = blockReduceSum(s2, sh);
    float m2  = s1 * (1.0f / Dd);
    float rs2 = rsqrtf(s2 * (1.0f / Dd) - m2 * m2 + 1e-5f);

#pragma unroll
    for (int j = 0; j < 4; j++) {
        int d = threadIdx.x + j * 256;
        xn[(size_t)row * Dd + d] = roundtf((t[j] - m2) * rs2 * g2[d] + b2[d]);
    }
}

// ---------------- SMEM-staged selective scan -------------------------------------
__global__ __launch_bounds__(256) void scan_smem_kernel(
    const float* __restrict__ de1, const float* __restrict__ de2,
    const float* __restrict__ z12, int ldz,
    const float* __restrict__ dbc1, const float* __restrict__ dbc2,
    const float* __restrict__ Alog1, const float* __restrict__ Alog2,
    const float* __restrict__ Dp1, const float* __restrict__ Dp2,
    float* __restrict__ gg1, float* __restrict__ gg2)
{
    __shared__ float deS[2][SCH][16];
    __shared__ float zS [2][SCH][16];
    __shared__ float bcS[2][SCH][32];
    __shared__ float ggS[SCH][16];

    const int tid = threadIdx.x;
    const int u   = tid >> 4;
    const int n   = tid & 15;

    const int bx = blockIdx.x;         // 0..511
    const int et = bx & 127;
    const int b  = (bx >> 7) & 1;
    const int br = bx >> 8;
    const int e0 = et * 16;

    const float* de   = br ? de2  : de1;
    const float* z    = z12 + (br ? Ee : 0);
    const float* dbc  = br ? dbc2 : dbc1;
    const float* Alog = br ? Alog2 : Alog1;
    const float* Dp   = br ? Dp2  : Dp1;
    float*       gg   = br ? gg2  : gg1;

    const int e = e0 + u;
    const float A_n  = -__expf(Alog[e * Nn + n]);
    const float Dp_e = Dp[e];

    const size_t rowBase = (size_t)b * Ss;

    uint32_t deSm = (uint32_t)__cvta_generic_to_shared(&deS[0][0][0]);
    uint32_t zSm  = (uint32_t)__cvta_generic_to_shared(&zS[0][0][0]);
    uint32_t bcSm = (uint32_t)__cvta_generic_to_shared(&bcS[0][0][0]);

    const int lr  = tid >> 2;
    const int lp  = (tid & 3) * 4;
    const int br0 = (tid * 2) >> 3;
    const int bp0 = ((tid * 2) & 7) * 4;
    const int br1 = (tid * 2 + 1) >> 3;
    const int bp1 = ((tid * 2 + 1) & 7) * 4;

    auto loadChunk = [&](int c, int buf) {
        int s = br ? (Ss - 1 - (c * SCH + lr)) : (c * SCH + lr);
        const float* gd = de + (rowBase + s) * Ee + e0 + lp;
        const float* gz = z  + (rowBase + s) * (size_t)ldz + e0 + lp;
        CP16F(deSm + (uint32_t)((buf * SCH + lr) * 16 + lp) * 4u, gd);
        CP16F(zSm  + (uint32_t)((buf * SCH + lr) * 16 + lp) * 4u, gz);
        int s0 = br ? (Ss - 1 - (c * SCH + br0)) : (c * SCH + br0);
        int s1b = br ? (Ss - 1 - (c * SCH + br1)) : (c * SCH + br1);
        const float* g0 = dbc + (rowBase + s0) * DBCW + Rr + bp0;
        const float* g1 = dbc + (rowBase + s1b) * DBCW + Rr + bp1;
        CP16F(bcSm + (uint32_t)((buf * SCH + br0) * 32 + bp0) * 4u, g0);
        CP16F(bcSm + (uint32_t)((buf * SCH + br1) * 32 + bp1) * 4u, g1);
    };

    loadChunk(0, 0);
    asm volatile("cp.async.commit_group;");

    float h = 0.0f;

    for (int c = 0; c < NCH; c++) {
        if (c + 1 < NCH) {
            loadChunk(c + 1, (c + 1) & 1);
            asm volatile("cp.async.commit_group;");
            asm volatile("cp.async.wait_group 1;");
        } else {
            asm volatile("cp.async.wait_group 0;");
        }
        __syncthreads();

        const int buf = c & 1;
#pragma unroll 8
        for (int cs = 0; cs < SCH; cs++) {
            float dlt = deS[buf][cs][u];
            float uu  = zS[buf][cs][u];
            float Bv  = bcS[buf][cs][n];
            float Cv  = bcS[buf][cs][16 + n];

            h = __expf(dlt * A_n) * h + dlt * Bv * uu;
            float y = h * Cv;
            y += __shfl_xor_sync(0xffffffffu, y, 8);
            y += __shfl_xor_sync(0xffffffffu, y, 4);
            y += __shfl_xor_sync(0xffffffffu, y, 2);
            y += __shfl_xor_sync(0xffffffffu, y, 1);
            if (n == 0) ggS[cs][u] = y + uu * Dp_e;
        }
        __syncthreads();

        {
            int r = tid >> 2, p = (tid & 3) * 4;
            int s = br ? (Ss - 1 - (c * SCH + r)) : (c * SCH + r);
            *(float4*)&gg[(rowBase + s) * Ee + e0 + p] = *(float4*)&ggS[r][p];
        }
    }
}

// ---------------- acmb = silu(mx) * (gg1 + gg2), rounded --------------------------
__global__ void combine_kernel(const float4* __restrict__ mzx,
                               const float4* __restrict__ gg1,
                               const float4* __restrict__ gg2,
                               float4* __restrict__ a, int n4)
{
    int i = blockIdx.x * blockDim.x + threadIdx.x;
    if (i < n4) {
        int row  = i >> 9;              // / (Ee/4)
        int col4 = i & 511;
        float4 m = mzx[row * 1024 + 512 + col4];   // mx half (ld=4096 floats)
        float4 p = gg1[i], q = gg2[i], r;
        r.x = roundtf(siluf(m.x) * (p.x + q.x));
        r.y = roundtf(siluf(m.y) * (p.y + q.y));
        r.z = roundtf(siluf(m.z) * (p.z + q.z));
        r.w = roundtf(siluf(m.w) * (p.w + q.w));
        a[i] = r;
    }
}

// ---------------- out = x + gate * (tmp + skip) -----------------------------------
__global__ void final_kernel(const float4* __restrict__ x,
                             const float* __restrict__ ada,
                             const float4* __restrict__ tmp,
                             const float4* __restrict__ skip,
                             float4* __restrict__ out, int n4)
{
    int i = blockIdx.x * blockDim.x + threadIdx.x;
    if (i < n4) {
        int d4  = i & (Dd / 4 - 1);
        int b   = i >> 18;
        const float4 g = *(const float4*)&ada[b * THREED + 2 * Dd + d4 * 4];
        float4 xv = x[i], tv = tmp[i], sv = skip[i], o;
        o.x = xv.x + g.x * (tv.x + sv.x);
        o.y = xv.y + g.y * (tv.y + sv.y);
        o.z = xv.z + g.z * (tv.z + sv.z);
        o.w = xv.w + g.w * (tv.w + sv.w);
        out[i] = o;
    }
}

// ---------------- host launcher ----------------------------------------------------
extern "C" void kernel_launch(void* const* d_in, const int* in_sizes, int n_in,
                              void* d_out, int out_size)
{
    const float* x     = (const float*)d_in[0];
    const float* c     = (const float*)d_in[1];
    const float* n1g   = (const float*)d_in[3];
    const float* n1b   = (const float*)d_in[4];
    const float* n2g   = (const float*)d_in[5];
    const float* n2b   = (const float*)d_in[6];
    const float* Wx    = (const float*)d_in[7];
    const float* bx    = (const float*)d_in[8];
    const float* Wz    = (const float*)d_in[9];
    const float* bz    = (const float*)d_in[10];
    const float* Wf    = (const float*)d_in[11];
    const float* bf    = (const float*)d_in[12];
    const float* Wada  = (const float*)d_in[13];
    const float* bada  = (const float*)d_in[14];
    const float* Wc1   = (const float*)d_in[15];
    const float* bc1   = (const float*)d_in[16];
    const float* Wc2   = (const float*)d_in[17];
    const float* bc2   = (const float*)d_in[18];
    const float* Wdbc1 = (const float*)d_in[19];
    const float* Wdt1  = (const float*)d_in[20];
    const float* bdt1  = (const float*)d_in[21];
    const float* Alog1 = (const float*)d_in[22];
    const float* Dp1   = (const float*)d_in[23];
    const float* Wdbc2 = (const float*)d_in[24];
    const float* Wdt2  = (const float*)d_in[25];
    const float* bdt2  = (const float*)d_in[26];
    const float* Alog2 = (const float*)d_in[27];
    const float* Dp2   = (const float*)d_in[28];
    float* out = (float*)d_out;

    float *ada, *skip, *xn, *mzx, *z12, *dbc1, *dbc2;
    float *de1, *de2, *gg1, *gg2, *acmb, *tmp, *part;
    float *wzx, *wc12, *wdbc1, *wdbc2, *wdt1, *wdt2, *wf, *bzx, *bc12;
    cudaGetSymbolAddress((void**)&ada,  g_ada);
    cudaGetSymbolAddress((void**)&skip, g_skip);
    cudaGetSymbolAddress((void**)&xn,   g_xn);
    cudaGetSymbolAddress((void**)&mzx,  g_mzx);
    cudaGetSymbolAddress((void**)&z12,  g_z12);
    cudaGetSymbolAddress((void**)&dbc1, g_dbc1);
    cudaGetSymbolAddress((void**)&dbc2, g_dbc2);
    cudaGetSymbolAddress((void**)&de1,  g_del1);
    cudaGetSymbolAddress((void**)&de2,  g_del2);
    cudaGetSymbolAddress((void**)&gg1,  g_gg1);
    cudaGetSymbolAddress((void**)&gg2,  g_gg2);
    cudaGetSymbolAddress((void**)&acmb, g_acmb);
    cudaGetSymbolAddress((void**)&tmp,  g_tmp);
    cudaGetSymbolAddress((void**)&part, g_part);
    cudaGetSymbolAddress((void**)&wzx,   g_wzx);
    cudaGetSymbolAddress((void**)&wc12,  g_wc12);
    cudaGetSymbolAddress((void**)&wdbc1, g_wdbc1);
    cudaGetSymbolAddress((void**)&wdbc2, g_wdbc2);
    cudaGetSymbolAddress((void**)&wdt1,  g_wdt1);
    cudaGetSymbolAddress((void**)&wdt2,  g_wdt2);
    cudaGetSymbolAddress((void**)&wf,    g_wf);
    cudaGetSymbolAddress((void**)&bzx,   g_bzx);
    cudaGetSymbolAddress((void**)&bc12,  g_bc12);

    const int SMEM = 98304;   // 3-stage pipeline: 2 x 3 x 16KB
    cudaFuncSetAttribute(gemm_tf32, cudaFuncAttributeMaxDynamicSharedMemorySize, SMEM);

    // 1. fused weight round + bias concat (one launch)
    {
        RoundJobs jb;
        const float* srcs[NSEG] = { Wz, Wx, Wc1, Wc2, Wdbc1, Wdbc2, Wdt1, Wdt2, Wf,
                                    bz, bx, bc1, bc2 };
        float* dsts[NSEG] = { wzx, wzx + (size_t)Ee * Dd,
                              wc12, wc12 + (size_t)Ee * Ee,
                              wdbc1, wdbc2, wdt1, wdt2, wf,
                              bzx, bzx + Ee, bc12, bc12 + Ee };
        int sizes4[NSEG] = { Ee * Dd / 4, Ee * Dd / 4, Ee * Ee / 4, Ee * Ee / 4,
                             DBCW * Ee / 4, DBCW * Ee / 4, Ee * Rr / 4, Ee * Rr / 4,
                             Dd * Ee / 4, Ee / 4, Ee / 4, Ee / 4, Ee / 4 };
        int rnds[NSEG] = { 1,1,1,1,1,1,1,1,1, 0,0,0,0 };
        int off = 0;
        for (int s = 0; s < NSEG; s++) {
            jb.src[s] = (const float4*)srcs[s];
            jb.dst[s] = (float4*)dsts[s];
            jb.off[s] = off;
            jb.rnd[s] = rnds[s];
            off += sizes4[s];
        }
        jb.off[NSEG] = off;
        round_all_kernel<<<(off + 255) / 256, 256>>>(jb, off);
    }

    // 2. ada = silu(c) @ Wada^T + bada  (one warp -> both batch rows)
    ada_kernel<<<384, 256>>>(c, Wada, bada, ada);

    // 3. LN1 + modulate (-> skip) + LN2 (-> xn, rounded)
    ln_mod_kernel<<<BSr, 256>>>(x, n1g, n1b, n2g, n2b, ada, skip, xn);

    // 4. merged mz|mx  [2048, 4096] K=1024
    gemm_tf32<<<dim3(2 * Ee / 128, BSr / 128, 1), 256, SMEM>>>(
        xn, Dd, wzx, Dd, bzx, mzx, 2 * Ee, BSr, 2 * Ee, Dd, 0, Ee, 1, 0,
        nullptr, nullptr, nullptr, nullptr);

    // 5. merged z1|z2  [2048, 4096] K=2048 (A = mz half of mzx, lda=4096)
    gemm_tf32<<<dim3(2 * Ee / 128, BSr / 128, 1), 256, SMEM>>>(
        mzx, 2 * Ee, wc12, Ee, bc12, z12, 2 * Ee, BSr, 2 * Ee, Ee, 0, 2 * Ee, 1, 0,
        nullptr, nullptr, nullptr, nullptr);

    // 6. dbc (both branches, split-K=8, one launch: grid.z = 16)
    gemm_tf32<<<dim3(1, BSr / 128, 2 * KSPLIT), 256, SMEM>>>(
        z12, 2 * Ee, wdbc1, Ee, nullptr, part, DBCW, BSr, DBCW, Ee, 0, 0,
        KSPLIT, BSr * DBCW,
        z12 + Ee, wdbc2, nullptr, nullptr);

    // 7. reduce both branches -> dbc1, dbc2 (rounded)
    reduce_splitk2<<<(2 * BSr * DBCW + 255) / 256, 256>>>(part, dbc1, dbc2, BSr * DBCW);

    // 8. delta (both branches, one launch: grid.z = 2), softplus epilogue
    gemm_tf32<<<dim3(Ee / 128, BSr / 128, 2), 256, SMEM>>>(
        dbc1, DBCW, wdt1, Rr, bdt1, de1, Ee, BSr, Ee, Rr, 1, 0, 1, 0,
        dbc2, wdt2, bdt2, de2);

    // 9. both selective scans, SMEM-staged
    scan_smem_kernel<<<512, 256>>>(de1, de2, z12, 2 * Ee, dbc1, dbc2,
                                   Alog1, Alog2, Dp1, Dp2, gg1, gg2);

    // 10. acmb = silu(mx) * (gg1 + gg2), rounded
    combine_kernel<<<(BSr * Ee / 4 + 255) / 256, 256>>>(
        (const float4*)mzx, (const float4*)gg1, (const float4*)gg2,
        (float4*)acmb, BSr * Ee / 4);

    // 11. tmp = acmb @ Wf^T + bf  [2048, 1024] K=2048
    gemm_tf32<<<dim3(Dd / 128, BSr / 128, 1), 256, SMEM>>>(
        acmb, Ee, wf, Ee, bf, tmp, Dd, BSr, Dd, Ee, 0, 0, 1, 0,
        nullptr, nullptr, nullptr, nullptr);

    // 12. out = x + gate * (tmp + skip)
    final_kernel<<<(BSr * Dd / 4 + 255) / 256, 256>>>(
        (const float4*)x, ada, (const float4*)tmp, (const float4*)skip,
        (float4*)out, BSr * Dd / 4);
}